// round 3
// baseline (speedup 1.0000x reference)
#include <cuda_runtime.h>
#include <cuda_bf16.h>

#define N_NODES   100000
#define N_EDGES   3200000
#define N_FEATS   512
#define HIDDEN    256
#define N_CLASSES 64
#define K_STEPS   10
#define ALPHA     0.1f

// ---------------- static device scratch (no runtime allocation) ----------------
__device__ float  g_hmid[(size_t)N_NODES * HIDDEN];     // after GEMM1+relu
__device__ float  g_h0  [(size_t)N_NODES * N_CLASSES];  // after GEMM2 (teleport vec)
__device__ float  g_ha  [(size_t)N_NODES * N_CLASSES];
__device__ float  g_hb  [(size_t)N_NODES * N_CLASSES];
__device__ int    g_deg [N_NODES];
__device__ float  g_dinv[N_NODES];
__device__ int    g_rowptr[N_NODES + 1];
__device__ int    g_woff[N_NODES];
__device__ float2 g_csr[N_EDGES];   // .x = __int_as_float(src), .y = dinv[src]*dinv[dst]

// ---------------- graph preprocessing ----------------
__global__ void init_deg_kernel() {
    int i = blockIdx.x * blockDim.x + threadIdx.x;
    if (i < N_NODES) g_deg[i] = 1;   // self loop
}

__global__ void count_deg_kernel(const int* __restrict__ ei) {
    int e = blockIdx.x * blockDim.x + threadIdx.x;
    if (e < N_EDGES) {
        int d = ei[N_EDGES + e];
        atomicAdd(&g_deg[d], 1);
    }
}

__global__ void dinv_kernel() {
    int i = blockIdx.x * blockDim.x + threadIdx.x;
    if (i < N_NODES) g_dinv[i] = rsqrtf((float)g_deg[i]);
}

// single-block exclusive scan of (deg-1) -> rowptr, woff
__global__ void scan_kernel() {
    __shared__ int s[1024];
    __shared__ int sc;
    int t = threadIdx.x;
    if (t == 0) sc = 0;
    __syncthreads();
    for (int base = 0; base < N_NODES; base += 1024) {
        int carry = sc;
        int i = base + t;
        int v = (i < N_NODES) ? (g_deg[i] - 1) : 0;
        s[t] = v;
        __syncthreads();
        #pragma unroll
        for (int off = 1; off < 1024; off <<= 1) {
            int add = (t >= off) ? s[t - off] : 0;
            __syncthreads();
            s[t] += add;
            __syncthreads();
        }
        int incl = s[t];
        if (i < N_NODES) {
            int excl = carry + incl - v;
            g_rowptr[i] = excl;
            g_woff[i]   = excl;
        }
        __syncthreads();
        if (t == 1023) sc = carry + incl;
        __syncthreads();
    }
    if (t == 0) g_rowptr[N_NODES] = N_EDGES;
}

__global__ void scatter_kernel(const int* __restrict__ ei) {
    int e = blockIdx.x * blockDim.x + threadIdx.x;
    if (e >= N_EDGES) return;
    int s = ei[e];
    int d = ei[N_EDGES + e];
    float w = g_dinv[s] * g_dinv[d];
    int pos = atomicAdd(&g_woff[d], 1);
    g_csr[pos] = make_float2(__int_as_float(s), w);
}

// ---------------- GEMM: C[M,N] = act(A[M,K] @ B[K,N] + bias) ----------------
// BM=128, BN=64, BK=16, 256 threads, thread tile 8x4
template<int K, int N, bool RELU>
__global__ void gemm_kernel(const float* __restrict__ A, const float* __restrict__ B,
                            const float* __restrict__ bias, float* __restrict__ C,
                            int M) {
    const int BM = 128, BN = 64, BK = 16;
    __shared__ float As[BK][BM];
    __shared__ float Bs[BK][BN];
    int tid = threadIdx.x;
    int bm = blockIdx.y * BM;
    int bn = blockIdx.x * BN;
    int tx = tid % 16;       // N
    int ty = tid / 16;       // M
    float acc[8][4];
    #pragma unroll
    for (int i = 0; i < 8; i++)
        #pragma unroll
        for (int j = 0; j < 4; j++) acc[i][j] = 0.f;

    int ar = tid >> 1;             // 0..127 tile row
    int ak = (tid & 1) * 8;        // 0 or 8
    int bk = tid >> 4;             // 0..15
    int bn4 = (tid & 15) * 4;

    for (int k0 = 0; k0 < K; k0 += BK) {
        int grow = bm + ar;
        if (grow < M) {
            float4 v0 = *(const float4*)&A[(size_t)grow * K + k0 + ak];
            float4 v1 = *(const float4*)&A[(size_t)grow * K + k0 + ak + 4];
            As[ak + 0][ar] = v0.x; As[ak + 1][ar] = v0.y;
            As[ak + 2][ar] = v0.z; As[ak + 3][ar] = v0.w;
            As[ak + 4][ar] = v1.x; As[ak + 5][ar] = v1.y;
            As[ak + 6][ar] = v1.z; As[ak + 7][ar] = v1.w;
        } else {
            #pragma unroll
            for (int i = 0; i < 8; i++) As[ak + i][ar] = 0.f;
        }
        float4 bv = *(const float4*)&B[(size_t)(k0 + bk) * N + bn + bn4];
        *(float4*)&Bs[bk][bn4] = bv;
        __syncthreads();

        #pragma unroll
        for (int kk = 0; kk < BK; kk++) {
            float4 a0 = *(float4*)&As[kk][ty * 8];
            float4 a1 = *(float4*)&As[kk][ty * 8 + 4];
            float4 bb = *(float4*)&Bs[kk][tx * 4];
            float a[8] = {a0.x, a0.y, a0.z, a0.w, a1.x, a1.y, a1.z, a1.w};
            float b[4] = {bb.x, bb.y, bb.z, bb.w};
            #pragma unroll
            for (int i = 0; i < 8; i++)
                #pragma unroll
                for (int j = 0; j < 4; j++)
                    acc[i][j] += a[i] * b[j];
        }
        __syncthreads();
    }

    float bsv[4];
    #pragma unroll
    for (int j = 0; j < 4; j++) bsv[j] = bias[bn + tx * 4 + j];
    #pragma unroll
    for (int i = 0; i < 8; i++) {
        int row = bm + ty * 8 + i;
        if (row < M) {
            float4 o;
            float c0 = acc[i][0] + bsv[0];
            float c1 = acc[i][1] + bsv[1];
            float c2 = acc[i][2] + bsv[2];
            float c3 = acc[i][3] + bsv[3];
            if (RELU) {
                c0 = fmaxf(c0, 0.f); c1 = fmaxf(c1, 0.f);
                c2 = fmaxf(c2, 0.f); c3 = fmaxf(c3, 0.f);
            }
            o.x = c0; o.y = c1; o.z = c2; o.w = c3;
            *(float4*)&C[(size_t)row * N + bn + tx * 4] = o;
        }
    }
}

// ---------------- APPNP propagation step (pull, CSR, warp per node) ----------------
__global__ void step_kernel(const float2* __restrict__ hc, float2* __restrict__ hn) {
    int warp = (blockIdx.x * blockDim.x + threadIdx.x) >> 5;
    int lane = threadIdx.x & 31;
    if (warp >= N_NODES) return;
    int beg = g_rowptr[warp];
    int end = g_rowptr[warp + 1];
    float ax = 0.f, ay = 0.f;
    for (int e0 = beg; e0 < end; e0 += 32) {
        int idx = e0 + lane;
        float2 meta = (idx < end) ? g_csr[idx] : make_float2(0.f, 0.f);
        int srcreg = __float_as_int(meta.x);
        int n = min(32, end - e0);
        for (int j = 0; j < n; j++) {
            int   s = __shfl_sync(0xffffffffu, srcreg, j);
            float w = __shfl_sync(0xffffffffu, meta.y, j);
            float2 hv = hc[(size_t)s * 32 + lane];
            ax += w * hv.x;
            ay += w * hv.y;
        }
    }
    float dv = g_dinv[warp];
    float sw = dv * dv;                       // self-loop norm
    float2 hs = hc[(size_t)warp * 32 + lane];
    const float2* h02 = (const float2*)g_h0;
    float2 h0v = h02[(size_t)warp * 32 + lane];
    float2 o;
    o.x = (1.f - ALPHA) * (ax + sw * hs.x) + ALPHA * h0v.x;
    o.y = (1.f - ALPHA) * (ay + sw * hs.y) + ALPHA * h0v.y;
    hn[(size_t)warp * 32 + lane] = o;
}

// ---------------- log_softmax (warp per node, 64 classes) ----------------
__global__ void logsoftmax_kernel(const float2* __restrict__ h, float* __restrict__ out) {
    int warp = (blockIdx.x * blockDim.x + threadIdx.x) >> 5;
    int lane = threadIdx.x & 31;
    if (warp >= N_NODES) return;
    float2 v = h[(size_t)warp * 32 + lane];
    float m = fmaxf(v.x, v.y);
    #pragma unroll
    for (int off = 16; off > 0; off >>= 1)
        m = fmaxf(m, __shfl_xor_sync(0xffffffffu, m, off));
    float s = expf(v.x - m) + expf(v.y - m);
    #pragma unroll
    for (int off = 16; off > 0; off >>= 1)
        s += __shfl_xor_sync(0xffffffffu, s, off);
    float ls = logf(s);
    float2 o = make_float2(v.x - m - ls, v.y - m - ls);
    *(float2*)&out[(size_t)warp * 64 + 2 * lane] = o;
}

// ---------------- launch ----------------
extern "C" void kernel_launch(void* const* d_in, const int* in_sizes, int n_in,
                              void* d_out, int out_size) {
    const float* x  = (const float*)d_in[0];
    const int*   ei = (const int*)d_in[1];        // int32! (JAX x64 disabled)
    const float* W1 = (const float*)d_in[2];
    const float* b1 = (const float*)d_in[3];
    const float* W2 = (const float*)d_in[4];
    const float* b2 = (const float*)d_in[5];
    float* out = (float*)d_out;

    void *p_hmid, *p_h0, *p_ha, *p_hb;
    cudaGetSymbolAddress(&p_hmid, g_hmid);
    cudaGetSymbolAddress(&p_h0,   g_h0);
    cudaGetSymbolAddress(&p_ha,   g_ha);
    cudaGetSymbolAddress(&p_hb,   g_hb);
    float* hmid = (float*)p_hmid;
    float* h0   = (float*)p_h0;
    float* ha   = (float*)p_ha;
    float* hb   = (float*)p_hb;

    // --- graph preprocessing ---
    init_deg_kernel<<<(N_NODES + 255) / 256, 256>>>();
    count_deg_kernel<<<(N_EDGES + 255) / 256, 256>>>(ei);
    dinv_kernel<<<(N_NODES + 255) / 256, 256>>>();
    scan_kernel<<<1, 1024>>>();
    scatter_kernel<<<(N_EDGES + 255) / 256, 256>>>(ei);

    // --- MLP ---
    {
        dim3 grid1(HIDDEN / 64, (N_NODES + 127) / 128);
        gemm_kernel<N_FEATS, HIDDEN, true><<<grid1, 256>>>(x, W1, b1, hmid, N_NODES);
        dim3 grid2(N_CLASSES / 64, (N_NODES + 127) / 128);
        gemm_kernel<HIDDEN, N_CLASSES, false><<<grid2, 256>>>(hmid, W2, b2, h0, N_NODES);
    }

    // --- APPNP propagation ---
    int sblocks = (N_NODES * 32 + 255) / 256;   // warp per node
    const float2* cur = (const float2*)h0;
    float2* bufs[2] = {(float2*)ha, (float2*)hb};
    for (int t = 0; t < K_STEPS; t++) {
        float2* nxt = bufs[t & 1];
        step_kernel<<<sblocks, 256>>>(cur, nxt);
        cur = nxt;
    }

    // --- log_softmax ---
    logsoftmax_kernel<<<sblocks, 256>>>(cur, out);
}

// round 5
// speedup vs baseline: 1.0073x; 1.0073x over previous
#include <cuda_runtime.h>
#include <cuda_bf16.h>
#include <cstdint>

#define N_NODES   100000
#define N_EDGES   3200000
#define N_FEATS   512
#define HIDDEN    256
#define N_CLASSES 64
#define K_STEPS   10
#define ALPHA     0.1f

#define SCAN_BLOCKS 98   // 98*1024 >= N_NODES

// ---------------- static device scratch ----------------
__device__ float  g_hmid[(size_t)N_NODES * HIDDEN];
__device__ float  g_h0  [(size_t)N_NODES * N_CLASSES];
__device__ float  g_ha  [(size_t)N_NODES * N_CLASSES];
__device__ float  g_hb  [(size_t)N_NODES * N_CLASSES];
__device__ int    g_deg [N_NODES];
__device__ float  g_dinv[N_NODES];
__device__ int    g_rowptr[N_NODES + 1];
__device__ int    g_woff[N_NODES];
__device__ float2 g_csr[N_EDGES];   // .x=__int_as_float(src), .y=(1-alpha)*dinv*dinv
__device__ int    g_bsum[128];
__device__ int    g_boff[128];

// ---------------- graph preprocessing ----------------
__global__ void init_deg_kernel() {
    int i = blockIdx.x * blockDim.x + threadIdx.x;
    if (i < N_NODES) g_deg[i] = 1;
}
__global__ void count_deg_kernel(const int* __restrict__ ei) {
    int e = blockIdx.x * blockDim.x + threadIdx.x;
    if (e < N_EDGES) atomicAdd(&g_deg[ei[N_EDGES + e]], 1);
}
__global__ void dinv_kernel() {
    int i = blockIdx.x * blockDim.x + threadIdx.x;
    if (i < N_NODES) g_dinv[i] = rsqrtf((float)g_deg[i]);
}
__global__ void block_scan_kernel() {
    __shared__ int s[1024];
    int t = threadIdx.x;
    int i = blockIdx.x * 1024 + t;
    int v = (i < N_NODES) ? (g_deg[i] - 1) : 0;
    s[t] = v;
    __syncthreads();
    #pragma unroll
    for (int off = 1; off < 1024; off <<= 1) {
        int add = (t >= off) ? s[t - off] : 0;
        __syncthreads();
        s[t] += add;
        __syncthreads();
    }
    if (i < N_NODES) g_rowptr[i] = s[t] - v;   // exclusive, block-local
    if (t == 1023) g_bsum[blockIdx.x] = s[t];
}
__global__ void scan_sums_kernel() {
    __shared__ int s[128];
    int t = threadIdx.x;
    int v = (t < SCAN_BLOCKS) ? g_bsum[t] : 0;
    s[t] = v;
    __syncthreads();
    #pragma unroll
    for (int off = 1; off < 128; off <<= 1) {
        int add = (t >= off) ? s[t - off] : 0;
        __syncthreads();
        s[t] += add;
        __syncthreads();
    }
    g_boff[t] = s[t] - v;   // exclusive
}
__global__ void add_off_kernel() {
    int i = blockIdx.x * blockDim.x + threadIdx.x;
    if (i < N_NODES) {
        int r = g_rowptr[i] + g_boff[i >> 10];
        g_rowptr[i] = r;
        g_woff[i]   = r;
    }
    if (i == 0) g_rowptr[N_NODES] = N_EDGES;
}
__global__ void scatter_kernel(const int* __restrict__ ei) {
    int e = blockIdx.x * blockDim.x + threadIdx.x;
    if (e >= N_EDGES) return;
    int s = ei[e];
    int d = ei[N_EDGES + e];
    float w = (1.0f - ALPHA) * g_dinv[s] * g_dinv[d];
    int pos = atomicAdd(&g_woff[d], 1);
    g_csr[pos] = make_float2(__int_as_float(s), w);
}

// ---------------- GEMM1: fp32 FFMA2 (packed f32x2), BM=128 x BN=256(=HIDDEN) ----------------
// 512 threads; thread tile 8(M) x 8(N) with N split as cols {tx + 32*m}.
// Pair p holds cols (tx + 64p, tx + 64p + 32). Exact fp32 numerics.
__global__ void __launch_bounds__(512, 1) gemm1_kernel(const float* __restrict__ A,
                                                       const float* __restrict__ B,
                                                       const float* __restrict__ bias,
                                                       float* __restrict__ C) {
    const int BK = 16;
    __shared__ float As[BK][128];
    __shared__ float Bs[BK][HIDDEN];
    int tid = threadIdx.x;
    int bm = blockIdx.x * 128;
    int tx = tid & 31;          // lane -> base col
    int ty = tid >> 5;          // warp -> 8-row group

    unsigned long long acc[8][4];
    #pragma unroll
    for (int i = 0; i < 8; i++)
        #pragma unroll
        for (int p = 0; p < 4; p++) acc[i][p] = 0ULL;

    int arow = tid >> 2;            // 0..127
    int ak   = (tid & 3) * 4;       // 0,4,8,12
    int bk   = tid >> 5;            // 0..15
    int bn8  = (tid & 31) * 8;      // 0..248

    for (int k0 = 0; k0 < N_FEATS; k0 += BK) {
        // load A tile [128 x 16]
        float4 av = make_float4(0.f, 0.f, 0.f, 0.f);
        if (bm + arow < N_NODES)
            av = *(const float4*)&A[(size_t)(bm + arow) * N_FEATS + k0 + ak];
        As[ak + 0][arow] = av.x; As[ak + 1][arow] = av.y;
        As[ak + 2][arow] = av.z; As[ak + 3][arow] = av.w;
        // load B tile [16 x 256]
        *(float4*)&Bs[bk][bn8]     = *(const float4*)&B[(size_t)(k0 + bk) * HIDDEN + bn8];
        *(float4*)&Bs[bk][bn8 + 4] = *(const float4*)&B[(size_t)(k0 + bk) * HIDDEN + bn8 + 4];
        __syncthreads();

        #pragma unroll
        for (int kk = 0; kk < BK; kk++) {
            float a[8];
            *(float4*)(a)     = *(const float4*)&As[kk][ty * 8];
            *(float4*)(a + 4) = *(const float4*)&As[kk][ty * 8 + 4];
            float b[8];
            #pragma unroll
            for (int m = 0; m < 8; m++) b[m] = Bs[kk][tx + 32 * m];
            unsigned long long bp[4];
            #pragma unroll
            for (int p = 0; p < 4; p++)
                asm("mov.b64 %0, {%1, %2};" : "=l"(bp[p]) : "f"(b[2 * p]), "f"(b[2 * p + 1]));
            #pragma unroll
            for (int i = 0; i < 8; i++) {
                unsigned long long ap;
                asm("mov.b64 %0, {%1, %2};" : "=l"(ap) : "f"(a[i]), "f"(a[i]));
                #pragma unroll
                for (int p = 0; p < 4; p++)
                    asm("fma.rn.f32x2 %0, %1, %2, %0;" : "+l"(acc[i][p]) : "l"(ap), "l"(bp[p]));
            }
        }
        __syncthreads();
    }

    // epilogue: bias + relu, unpack pairs
    float blo[4], bhi[4];
    #pragma unroll
    for (int p = 0; p < 4; p++) {
        blo[p] = bias[tx + 64 * p];
        bhi[p] = bias[tx + 64 * p + 32];
    }
    #pragma unroll
    for (int i = 0; i < 8; i++) {
        int row = bm + ty * 8 + i;
        if (row < N_NODES) {
            float* dst = &C[(size_t)row * HIDDEN];
            #pragma unroll
            for (int p = 0; p < 4; p++) {
                float lo, hi;
                asm("mov.b64 {%0, %1}, %2;" : "=f"(lo), "=f"(hi) : "l"(acc[i][p]));
                dst[tx + 64 * p]      = fmaxf(lo + blo[p], 0.f);
                dst[tx + 64 * p + 32] = fmaxf(hi + bhi[p], 0.f);
            }
        }
    }
}

// ---------------- GEMM2 (SIMT fp32): C[M,64] = hmid @ W2 + b2 ----------------
template<int K, int N>
__global__ void gemm_kernel(const float* __restrict__ A, const float* __restrict__ B,
                            const float* __restrict__ bias, float* __restrict__ C, int M) {
    const int BM = 128, BN = 64, BK = 16;
    __shared__ float As[BK][BM];
    __shared__ float Bs[BK][BN];
    int tid = threadIdx.x;
    int bm = blockIdx.y * BM;
    int bn = blockIdx.x * BN;
    int tx = tid % 16;
    int ty = tid / 16;
    float acc[8][4];
    #pragma unroll
    for (int i = 0; i < 8; i++)
        #pragma unroll
        for (int j = 0; j < 4; j++) acc[i][j] = 0.f;
    int ar = tid >> 1, ak = (tid & 1) * 8, bk = tid >> 4, bn4 = (tid & 15) * 4;
    for (int k0 = 0; k0 < K; k0 += BK) {
        int grow = bm + ar;
        if (grow < M) {
            float4 v0 = *(const float4*)&A[(size_t)grow * K + k0 + ak];
            float4 v1 = *(const float4*)&A[(size_t)grow * K + k0 + ak + 4];
            As[ak + 0][ar] = v0.x; As[ak + 1][ar] = v0.y; As[ak + 2][ar] = v0.z; As[ak + 3][ar] = v0.w;
            As[ak + 4][ar] = v1.x; As[ak + 5][ar] = v1.y; As[ak + 6][ar] = v1.z; As[ak + 7][ar] = v1.w;
        } else {
            #pragma unroll
            for (int i = 0; i < 8; i++) As[ak + i][ar] = 0.f;
        }
        *(float4*)&Bs[bk][bn4] = *(const float4*)&B[(size_t)(k0 + bk) * N + bn + bn4];
        __syncthreads();
        #pragma unroll
        for (int kk = 0; kk < BK; kk++) {
            float4 a0 = *(float4*)&As[kk][ty * 8];
            float4 a1 = *(float4*)&As[kk][ty * 8 + 4];
            float4 bb = *(float4*)&Bs[kk][tx * 4];
            float a[8] = {a0.x, a0.y, a0.z, a0.w, a1.x, a1.y, a1.z, a1.w};
            float b[4] = {bb.x, bb.y, bb.z, bb.w};
            #pragma unroll
            for (int i = 0; i < 8; i++)
                #pragma unroll
                for (int j = 0; j < 4; j++)
                    acc[i][j] += a[i] * b[j];
        }
        __syncthreads();
    }
    float bsv[4];
    #pragma unroll
    for (int j = 0; j < 4; j++) bsv[j] = bias[bn + tx * 4 + j];
    #pragma unroll
    for (int i = 0; i < 8; i++) {
        int row = bm + ty * 8 + i;
        if (row < M) {
            float4 o = make_float4(acc[i][0] + bsv[0], acc[i][1] + bsv[1],
                                   acc[i][2] + bsv[2], acc[i][3] + bsv[3]);
            *(float4*)&C[(size_t)row * N + bn + tx * 4] = o;
        }
    }
}

// ---------------- APPNP propagation (pull, CSR, warp per node) ----------------
__device__ __forceinline__ float2 step_body(int node, int lane, const float2* __restrict__ hc) {
    int beg = g_rowptr[node];
    int end = g_rowptr[node + 1];
    float ax = 0.f, ay = 0.f;
    for (int e0 = beg; e0 < end; e0 += 32) {
        int idx = e0 + lane;
        float2 meta = (idx < end) ? g_csr[idx] : make_float2(0.f, 0.f);
        int srcreg = __float_as_int(meta.x);
        int n = min(32, end - e0);
        for (int j = 0; j < n; j++) {
            int   s = __shfl_sync(0xffffffffu, srcreg, j);
            float w = __shfl_sync(0xffffffffu, meta.y, j);
            float2 hv = hc[(size_t)s * 32 + lane];
            ax += w * hv.x;
            ay += w * hv.y;
        }
    }
    float dv = g_dinv[node];
    float sw = (1.0f - ALPHA) * dv * dv;
    float2 hs = hc[(size_t)node * 32 + lane];
    const float2* h02 = (const float2*)g_h0;
    float2 h0v = h02[(size_t)node * 32 + lane];
    float2 o;
    o.x = ax + sw * hs.x + ALPHA * h0v.x;
    o.y = ay + sw * hs.y + ALPHA * h0v.y;
    return o;
}

__global__ void step_kernel(const float2* __restrict__ hc, float2* __restrict__ hn) {
    int node = (blockIdx.x * blockDim.x + threadIdx.x) >> 5;
    int lane = threadIdx.x & 31;
    if (node >= N_NODES) return;
    hn[(size_t)node * 32 + lane] = step_body(node, lane, hc);
}

__global__ void step_last_kernel(const float2* __restrict__ hc, float* __restrict__ out) {
    int node = (blockIdx.x * blockDim.x + threadIdx.x) >> 5;
    int lane = threadIdx.x & 31;
    if (node >= N_NODES) return;
    float2 v = step_body(node, lane, hc);
    float m = fmaxf(v.x, v.y);
    #pragma unroll
    for (int off = 16; off > 0; off >>= 1)
        m = fmaxf(m, __shfl_xor_sync(0xffffffffu, m, off));
    float s = expf(v.x - m) + expf(v.y - m);
    #pragma unroll
    for (int off = 16; off > 0; off >>= 1)
        s += __shfl_xor_sync(0xffffffffu, s, off);
    float ls = logf(s) + m;
    float2 o = make_float2(v.x - ls, v.y - ls);
    *(float2*)&out[(size_t)node * 64 + 2 * lane] = o;
}

// ---------------- launch ----------------
extern "C" void kernel_launch(void* const* d_in, const int* in_sizes, int n_in,
                              void* d_out, int out_size) {
    const float* x  = (const float*)d_in[0];
    const int*   ei = (const int*)d_in[1];
    const float* W1 = (const float*)d_in[2];
    const float* b1 = (const float*)d_in[3];
    const float* W2 = (const float*)d_in[4];
    const float* b2 = (const float*)d_in[5];
    float* out = (float*)d_out;

    void *p_hmid, *p_h0, *p_ha, *p_hb;
    cudaGetSymbolAddress(&p_hmid, g_hmid);
    cudaGetSymbolAddress(&p_h0,   g_h0);
    cudaGetSymbolAddress(&p_ha,   g_ha);
    cudaGetSymbolAddress(&p_hb,   g_hb);
    float* hmid = (float*)p_hmid;
    float* h0   = (float*)p_h0;

    // launches 0-4 (keeps gemm1 at index 5 for ncu -s 5)
    init_deg_kernel<<<(N_NODES + 255) / 256, 256>>>();
    count_deg_kernel<<<(N_EDGES + 255) / 256, 256>>>(ei);
    dinv_kernel<<<(N_NODES + 255) / 256, 256>>>();
    block_scan_kernel<<<SCAN_BLOCKS, 1024>>>();
    scan_sums_kernel<<<1, 128>>>();

    // 5: GEMM1 (FFMA2)
    gemm1_kernel<<<(N_NODES + 127) / 128, 512>>>(x, W1, b1, hmid);

    add_off_kernel<<<(N_NODES + 255) / 256, 256>>>();
    scatter_kernel<<<(N_EDGES + 255) / 256, 256>>>(ei);

    // GEMM2
    {
        dim3 grid2(N_CLASSES / 64, (N_NODES + 127) / 128);
        gemm_kernel<HIDDEN, N_CLASSES><<<grid2, 256>>>(hmid, W2, b2, h0, N_NODES);
    }

    // APPNP propagation: 9 steps + fused last
    int sblocks = (N_NODES * 32 + 255) / 256;
    const float2* cur = (const float2*)h0;
    float2* bufs[2] = {(float2*)p_ha, (float2*)p_hb};
    for (int t = 0; t < K_STEPS - 1; t++) {
        float2* nxt = bufs[t & 1];
        step_kernel<<<sblocks, 256>>>(cur, nxt);
        cur = nxt;
    }
    step_last_kernel<<<sblocks, 256>>>(cur, out);
}

// round 7
// speedup vs baseline: 1.2552x; 1.2462x over previous
#include <cuda_runtime.h>
#include <cuda_bf16.h>
#include <cstdint>

#define N_NODES   100000
#define N_EDGES   3200000
#define N_FEATS   512
#define HIDDEN    256
#define N_CLASSES 64
#define K_STEPS   10
#define ALPHA     0.1f

#define SCAN_BLOCKS 98   // 98*1024 >= N_NODES

// ---------------- static device scratch ----------------
__device__ float  g_hmid[(size_t)N_NODES * HIDDEN];
__device__ __align__(16) float g_h0[(size_t)N_NODES * N_CLASSES];
__device__ __align__(16) float g_ha[(size_t)N_NODES * N_CLASSES];
__device__ __align__(16) float g_hb[(size_t)N_NODES * N_CLASSES];
__device__ int    g_deg [N_NODES];
__device__ float  g_dinv[N_NODES];
__device__ int    g_rowptr[N_NODES + 1];
__device__ int    g_woff[N_NODES];
__device__ float2 g_csr[N_EDGES];   // .x=__int_as_float(src), .y=(1-alpha)*dinv*dinv
__device__ int    g_bsum[128];
__device__ int    g_boff[128];

// ---------------- graph preprocessing ----------------
__global__ void init_deg_kernel() {
    int i = blockIdx.x * blockDim.x + threadIdx.x;
    if (i < N_NODES) g_deg[i] = 1;
}
__global__ void count_deg_kernel(const int* __restrict__ ei) {
    int e = blockIdx.x * blockDim.x + threadIdx.x;
    if (e < N_EDGES) atomicAdd(&g_deg[ei[N_EDGES + e]], 1);
}
__global__ void dinv_kernel() {
    int i = blockIdx.x * blockDim.x + threadIdx.x;
    if (i < N_NODES) g_dinv[i] = rsqrtf((float)g_deg[i]);
}
__global__ void block_scan_kernel() {
    __shared__ int s[1024];
    int t = threadIdx.x;
    int i = blockIdx.x * 1024 + t;
    int v = (i < N_NODES) ? (g_deg[i] - 1) : 0;
    s[t] = v;
    __syncthreads();
    #pragma unroll
    for (int off = 1; off < 1024; off <<= 1) {
        int add = (t >= off) ? s[t - off] : 0;
        __syncthreads();
        s[t] += add;
        __syncthreads();
    }
    if (i < N_NODES) g_rowptr[i] = s[t] - v;   // exclusive, block-local
    if (t == 1023) g_bsum[blockIdx.x] = s[t];
}
__global__ void scan_sums_kernel() {
    __shared__ int s[128];
    int t = threadIdx.x;
    int v = (t < SCAN_BLOCKS) ? g_bsum[t] : 0;
    s[t] = v;
    __syncthreads();
    #pragma unroll
    for (int off = 1; off < 128; off <<= 1) {
        int add = (t >= off) ? s[t - off] : 0;
        __syncthreads();
        s[t] += add;
        __syncthreads();
    }
    g_boff[t] = s[t] - v;   // exclusive
}
__global__ void add_off_kernel() {
    int i = blockIdx.x * blockDim.x + threadIdx.x;
    if (i < N_NODES) {
        int r = g_rowptr[i] + g_boff[i >> 10];
        g_rowptr[i] = r;
        g_woff[i]   = r;
    }
    if (i == 0) g_rowptr[N_NODES] = N_EDGES;
}
__global__ void scatter_kernel(const int* __restrict__ ei) {
    int e = blockIdx.x * blockDim.x + threadIdx.x;
    if (e >= N_EDGES) return;
    int s = ei[e];
    int d = ei[N_EDGES + e];
    float w = (1.0f - ALPHA) * g_dinv[s] * g_dinv[d];
    int pos = atomicAdd(&g_woff[d], 1);
    g_csr[pos] = make_float2(__int_as_float(s), w);
}

// ---------------- GEMM1: fp32 FFMA2 (packed f32x2), BM=128 x BN=256(=HIDDEN) ----------------
__global__ void __launch_bounds__(512, 1) gemm1_kernel(const float* __restrict__ A,
                                                       const float* __restrict__ B,
                                                       const float* __restrict__ bias,
                                                       float* __restrict__ C) {
    const int BK = 16;
    __shared__ float As[BK][128];
    __shared__ float Bs[BK][HIDDEN];
    int tid = threadIdx.x;
    int bm = blockIdx.x * 128;
    int tx = tid & 31;
    int ty = tid >> 5;

    unsigned long long acc[8][4];
    #pragma unroll
    for (int i = 0; i < 8; i++)
        #pragma unroll
        for (int p = 0; p < 4; p++) acc[i][p] = 0ULL;

    int arow = tid >> 2;
    int ak   = (tid & 3) * 4;
    int bk   = tid >> 5;
    int bn8  = (tid & 31) * 8;

    for (int k0 = 0; k0 < N_FEATS; k0 += BK) {
        float4 av = make_float4(0.f, 0.f, 0.f, 0.f);
        if (bm + arow < N_NODES)
            av = *(const float4*)&A[(size_t)(bm + arow) * N_FEATS + k0 + ak];
        As[ak + 0][arow] = av.x; As[ak + 1][arow] = av.y;
        As[ak + 2][arow] = av.z; As[ak + 3][arow] = av.w;
        *(float4*)&Bs[bk][bn8]     = *(const float4*)&B[(size_t)(k0 + bk) * HIDDEN + bn8];
        *(float4*)&Bs[bk][bn8 + 4] = *(const float4*)&B[(size_t)(k0 + bk) * HIDDEN + bn8 + 4];
        __syncthreads();

        #pragma unroll
        for (int kk = 0; kk < BK; kk++) {
            float a[8];
            *(float4*)(a)     = *(const float4*)&As[kk][ty * 8];
            *(float4*)(a + 4) = *(const float4*)&As[kk][ty * 8 + 4];
            float b[8];
            #pragma unroll
            for (int m = 0; m < 8; m++) b[m] = Bs[kk][tx + 32 * m];
            unsigned long long bp[4];
            #pragma unroll
            for (int p = 0; p < 4; p++)
                asm("mov.b64 %0, {%1, %2};" : "=l"(bp[p]) : "f"(b[2 * p]), "f"(b[2 * p + 1]));
            #pragma unroll
            for (int i = 0; i < 8; i++) {
                unsigned long long ap;
                asm("mov.b64 %0, {%1, %2};" : "=l"(ap) : "f"(a[i]), "f"(a[i]));
                #pragma unroll
                for (int p = 0; p < 4; p++)
                    asm("fma.rn.f32x2 %0, %1, %2, %0;" : "+l"(acc[i][p]) : "l"(ap), "l"(bp[p]));
            }
        }
        __syncthreads();
    }

    float blo[4], bhi[4];
    #pragma unroll
    for (int p = 0; p < 4; p++) {
        blo[p] = bias[tx + 64 * p];
        bhi[p] = bias[tx + 64 * p + 32];
    }
    #pragma unroll
    for (int i = 0; i < 8; i++) {
        int row = bm + ty * 8 + i;
        if (row < N_NODES) {
            float* dst = &C[(size_t)row * HIDDEN];
            #pragma unroll
            for (int p = 0; p < 4; p++) {
                float lo, hi;
                asm("mov.b64 {%0, %1}, %2;" : "=f"(lo), "=f"(hi) : "l"(acc[i][p]));
                dst[tx + 64 * p]      = fmaxf(lo + blo[p], 0.f);
                dst[tx + 64 * p + 32] = fmaxf(hi + bhi[p], 0.f);
            }
        }
    }
}

// ---------------- GEMM2 (SIMT fp32): C[M,64] = hmid @ W2 + b2 ----------------
template<int K, int N>
__global__ void gemm_kernel(const float* __restrict__ A, const float* __restrict__ B,
                            const float* __restrict__ bias, float* __restrict__ C, int M) {
    const int BM = 128, BN = 64, BK = 16;
    __shared__ float As[BK][BM];
    __shared__ float Bs[BK][BN];
    int tid = threadIdx.x;
    int bm = blockIdx.y * BM;
    int bn = blockIdx.x * BN;
    int tx = tid % 16;
    int ty = tid / 16;
    float acc[8][4];
    #pragma unroll
    for (int i = 0; i < 8; i++)
        #pragma unroll
        for (int j = 0; j < 4; j++) acc[i][j] = 0.f;
    int ar = tid >> 1, ak = (tid & 1) * 8, bk = tid >> 4, bn4 = (tid & 15) * 4;
    for (int k0 = 0; k0 < K; k0 += BK) {
        int grow = bm + ar;
        if (grow < M) {
            float4 v0 = *(const float4*)&A[(size_t)grow * K + k0 + ak];
            float4 v1 = *(const float4*)&A[(size_t)grow * K + k0 + ak + 4];
            As[ak + 0][ar] = v0.x; As[ak + 1][ar] = v0.y; As[ak + 2][ar] = v0.z; As[ak + 3][ar] = v0.w;
            As[ak + 4][ar] = v1.x; As[ak + 5][ar] = v1.y; As[ak + 6][ar] = v1.z; As[ak + 7][ar] = v1.w;
        } else {
            #pragma unroll
            for (int i = 0; i < 8; i++) As[ak + i][ar] = 0.f;
        }
        *(float4*)&Bs[bk][bn4] = *(const float4*)&B[(size_t)(k0 + bk) * N + bn + bn4];
        __syncthreads();
        #pragma unroll
        for (int kk = 0; kk < BK; kk++) {
            float4 a0 = *(float4*)&As[kk][ty * 8];
            float4 a1 = *(float4*)&As[kk][ty * 8 + 4];
            float4 bb = *(float4*)&Bs[kk][tx * 4];
            float a[8] = {a0.x, a0.y, a0.z, a0.w, a1.x, a1.y, a1.z, a1.w};
            float b[4] = {bb.x, bb.y, bb.z, bb.w};
            #pragma unroll
            for (int i = 0; i < 8; i++)
                #pragma unroll
                for (int j = 0; j < 4; j++)
                    acc[i][j] += a[i] * b[j];
        }
        __syncthreads();
    }
    float bsv[4];
    #pragma unroll
    for (int j = 0; j < 4; j++) bsv[j] = bias[bn + tx * 4 + j];
    #pragma unroll
    for (int i = 0; i < 8; i++) {
        int row = bm + ty * 8 + i;
        if (row < M) {
            float4 o = make_float4(acc[i][0] + bsv[0], acc[i][1] + bsv[1],
                                   acc[i][2] + bsv[2], acc[i][3] + bsv[3]);
            *(float4*)&C[(size_t)row * N + bn + tx * 4] = o;
        }
    }
}

// ---------------- APPNP step: half-warp per node, float4 lanes ----------------
// CRITICAL: the two half-warps of a warp process DIFFERENT nodes with different
// edge-loop trip counts, so every shuffle must use the 16-lane SEGMENT mask,
// not 0xffffffff (full-mask shfl across divergent half-warps is UB -> the R6 crash).
__device__ __forceinline__ float4 step_body16(int node, int hl, unsigned mk,
                                              const float4* __restrict__ hc4) {
    int beg = g_rowptr[node];
    int end = g_rowptr[node + 1];
    float ax = 0.f, ay = 0.f, az = 0.f, aw = 0.f;
    for (int e0 = beg; e0 < end; e0 += 16) {
        int idx = e0 + hl;
        float2 meta = (idx < end) ? g_csr[idx] : make_float2(__int_as_float(0), 0.f);
        int   srcreg = __float_as_int(meta.x);
        float wreg   = meta.y;
        #pragma unroll
        for (int j = 0; j < 16; j++) {
            int   s = __shfl_sync(mk, srcreg, j, 16);
            float w = __shfl_sync(mk, wreg,   j, 16);
            float4 hv = hc4[(size_t)s * 16 + hl];
            ax = fmaf(w, hv.x, ax);
            ay = fmaf(w, hv.y, ay);
            az = fmaf(w, hv.z, az);
            aw = fmaf(w, hv.w, aw);
        }
    }
    float dv = g_dinv[node];
    float sw = (1.0f - ALPHA) * dv * dv;
    float4 hs  = hc4[(size_t)node * 16 + hl];
    const float4* h04 = (const float4*)g_h0;
    float4 h0v = h04[(size_t)node * 16 + hl];
    float4 o;
    o.x = ax + sw * hs.x + ALPHA * h0v.x;
    o.y = ay + sw * hs.y + ALPHA * h0v.y;
    o.z = az + sw * hs.z + ALPHA * h0v.z;
    o.w = aw + sw * hs.w + ALPHA * h0v.w;
    return o;
}

__global__ void __launch_bounds__(256) step_kernel(const float4* __restrict__ hc,
                                                   float4* __restrict__ hn) {
    int gt = blockIdx.x * blockDim.x + threadIdx.x;
    int node = gt >> 4;
    int hl = threadIdx.x & 15;
    unsigned mk = 0xFFFFu << (threadIdx.x & 16);
    if (node >= N_NODES) return;
    hn[(size_t)node * 16 + hl] = step_body16(node, hl, mk, hc);
}

__global__ void __launch_bounds__(256) step_last_kernel(const float4* __restrict__ hc,
                                                        float* __restrict__ out) {
    int gt = blockIdx.x * blockDim.x + threadIdx.x;
    int node = gt >> 4;
    int hl = threadIdx.x & 15;
    unsigned mk = 0xFFFFu << (threadIdx.x & 16);
    if (node >= N_NODES) return;
    float4 v = step_body16(node, hl, mk, hc);
    float m = fmaxf(fmaxf(v.x, v.y), fmaxf(v.z, v.w));
    #pragma unroll
    for (int off = 8; off > 0; off >>= 1)
        m = fmaxf(m, __shfl_xor_sync(mk, m, off, 16));
    float s = expf(v.x - m) + expf(v.y - m) + expf(v.z - m) + expf(v.w - m);
    #pragma unroll
    for (int off = 8; off > 0; off >>= 1)
        s += __shfl_xor_sync(mk, s, off, 16);
    float ls = logf(s) + m;
    float4 o = make_float4(v.x - ls, v.y - ls, v.z - ls, v.w - ls);
    *(float4*)&out[(size_t)node * 64 + 4 * hl] = o;
}

// ---------------- launch ----------------
extern "C" void kernel_launch(void* const* d_in, const int* in_sizes, int n_in,
                              void* d_out, int out_size) {
    const float* x  = (const float*)d_in[0];
    const int*   ei = (const int*)d_in[1];
    const float* W1 = (const float*)d_in[2];
    const float* b1 = (const float*)d_in[3];
    const float* W2 = (const float*)d_in[4];
    const float* b2 = (const float*)d_in[5];
    float* out = (float*)d_out;

    void *p_hmid, *p_h0, *p_ha, *p_hb;
    cudaGetSymbolAddress(&p_hmid, g_hmid);
    cudaGetSymbolAddress(&p_h0,   g_h0);
    cudaGetSymbolAddress(&p_ha,   g_ha);
    cudaGetSymbolAddress(&p_hb,   g_hb);
    float* hmid = (float*)p_hmid;
    float* h0   = (float*)p_h0;

    init_deg_kernel<<<(N_NODES + 255) / 256, 256>>>();                 // 0
    count_deg_kernel<<<(N_EDGES + 255) / 256, 256>>>(ei);              // 1
    dinv_kernel<<<(N_NODES + 255) / 256, 256>>>();                     // 2
    gemm1_kernel<<<(N_NODES + 127) / 128, 512>>>(x, W1, b1, hmid);     // 3  <- profile target
    block_scan_kernel<<<SCAN_BLOCKS, 1024>>>();                        // 4
    scan_sums_kernel<<<1, 128>>>();                                    // 5
    add_off_kernel<<<(N_NODES + 255) / 256, 256>>>();                  // 6
    scatter_kernel<<<(N_EDGES + 255) / 256, 256>>>(ei);                // 7

    {
        dim3 grid2(N_CLASSES / 64, (N_NODES + 127) / 128);
        gemm_kernel<HIDDEN, N_CLASSES><<<grid2, 256>>>(hmid, W2, b2, h0, N_NODES);
    }

    int sblocks = (N_NODES * 16 + 255) / 256;
    const float4* cur = (const float4*)h0;
    float4* bufs[2] = {(float4*)p_ha, (float4*)p_hb};
    for (int t = 0; t < K_STEPS - 1; t++) {
        float4* nxt = bufs[t & 1];
        step_kernel<<<sblocks, 256>>>(cur, nxt);
        cur = nxt;
    }
    step_last_kernel<<<sblocks, 256>>>(cur, out);
}

// round 8
// speedup vs baseline: 1.5325x; 1.2209x over previous
#include <cuda_runtime.h>
#include <cuda_bf16.h>
#include <cstdint>

#define N_NODES   100000
#define N_EDGES   3200000
#define N_FEATS   512
#define HIDDEN    256
#define N_CLASSES 64
#define K_STEPS   10
#define ALPHA     0.1f

#define SCAN_BLOCKS 98   // 98*1024 >= N_NODES

// ---------------- static device scratch ----------------
__device__ float  g_hmid[(size_t)N_NODES * HIDDEN];
__device__ __align__(16) float g_h0[(size_t)N_NODES * N_CLASSES];
__device__ __align__(16) float g_ha[(size_t)N_NODES * N_CLASSES];
__device__ __align__(16) float g_hb[(size_t)N_NODES * N_CLASSES];
__device__ int    g_deg [N_NODES];
__device__ float  g_dinv[N_NODES];
__device__ int    g_rowptr[N_NODES + 1];
__device__ int    g_woff[N_NODES];
__device__ float2 g_csr[N_EDGES];   // .x=__int_as_float(src), .y=(1-alpha)*dinv*dinv
__device__ int    g_bsum[128];
__device__ int    g_boff[128];
__device__ __align__(16) __nv_bfloat16 g_w1t_hi[(size_t)HIDDEN * N_FEATS];  // [n][k]
__device__ __align__(16) __nv_bfloat16 g_w1t_lo[(size_t)HIDDEN * N_FEATS];

__device__ __forceinline__ uint32_t smem_u32(const void* p) {
    uint32_t a;
    asm("{ .reg .u64 t; cvta.to.shared.u64 t, %1; cvt.u32.u64 %0, t; }" : "=r"(a) : "l"(p));
    return a;
}

// ---------------- W1 transpose + bf16 split ----------------
__global__ void splitT_w1_kernel(const float* __restrict__ W1) {
    int i = blockIdx.x * blockDim.x + threadIdx.x;
    if (i >= N_FEATS * HIDDEN) return;
    int k = i / HIDDEN, n = i % HIDDEN;
    float v = W1[i];
    __nv_bfloat16 h = __float2bfloat16(v);
    g_w1t_hi[(size_t)n * N_FEATS + k] = h;
    g_w1t_lo[(size_t)n * N_FEATS + k] = __float2bfloat16(v - __bfloat162float(h));
}

// ---------------- graph preprocessing ----------------
__global__ void init_deg_kernel() {
    int i = blockIdx.x * blockDim.x + threadIdx.x;
    if (i < N_NODES) g_deg[i] = 1;
}
__global__ void count_deg_kernel(const int* __restrict__ ei) {
    int e = blockIdx.x * blockDim.x + threadIdx.x;
    if (e < N_EDGES) atomicAdd(&g_deg[ei[N_EDGES + e]], 1);
}
__global__ void dinv_kernel() {
    int i = blockIdx.x * blockDim.x + threadIdx.x;
    if (i < N_NODES) g_dinv[i] = rsqrtf((float)g_deg[i]);
}
__global__ void block_scan_kernel() {
    __shared__ int s[1024];
    int t = threadIdx.x;
    int i = blockIdx.x * 1024 + t;
    int v = (i < N_NODES) ? (g_deg[i] - 1) : 0;
    s[t] = v;
    __syncthreads();
    #pragma unroll
    for (int off = 1; off < 1024; off <<= 1) {
        int add = (t >= off) ? s[t - off] : 0;
        __syncthreads();
        s[t] += add;
        __syncthreads();
    }
    if (i < N_NODES) g_rowptr[i] = s[t] - v;
    if (t == 1023) g_bsum[blockIdx.x] = s[t];
}
__global__ void scan_sums_kernel() {
    __shared__ int s[128];
    int t = threadIdx.x;
    int v = (t < SCAN_BLOCKS) ? g_bsum[t] : 0;
    s[t] = v;
    __syncthreads();
    #pragma unroll
    for (int off = 1; off < 128; off <<= 1) {
        int add = (t >= off) ? s[t - off] : 0;
        __syncthreads();
        s[t] += add;
        __syncthreads();
    }
    g_boff[t] = s[t] - v;
}
__global__ void add_off_kernel() {
    int i = blockIdx.x * blockDim.x + threadIdx.x;
    if (i < N_NODES) {
        int r = g_rowptr[i] + g_boff[i >> 10];
        g_rowptr[i] = r;
        g_woff[i]   = r;
    }
    if (i == 0) g_rowptr[N_NODES] = N_EDGES;
}
__global__ void scatter_kernel(const int* __restrict__ ei) {
    int e = blockIdx.x * blockDim.x + threadIdx.x;
    if (e >= N_EDGES) return;
    int s = ei[e];
    int d = ei[N_EDGES + e];
    float w = (1.0f - ALPHA) * g_dinv[s] * g_dinv[d];
    int pos = atomicAdd(&g_woff[d], 1);
    g_csr[pos] = make_float2(__int_as_float(s), w);
}

// ---------------- GEMM1: mma.sync bf16 3-split, BM=128 BN=128 BK=32 ----------------
// C = relu(x @ W1 + b1). 8 warps as 4(M)x2(N); warp tile 32x64; m16n8k16 mma.
#define ASTR 40   // smem row stride in bf16 elements (32 data + 8 pad) -> conflict-free ldmatrix

__device__ __forceinline__ void mma16816(float* c, const uint32_t* a, const uint32_t* b) {
    asm volatile("mma.sync.aligned.m16n8k16.row.col.f32.bf16.bf16.f32 "
        "{%0,%1,%2,%3},{%4,%5,%6,%7},{%8,%9},{%0,%1,%2,%3};"
        : "+f"(c[0]), "+f"(c[1]), "+f"(c[2]), "+f"(c[3])
        : "r"(a[0]), "r"(a[1]), "r"(a[2]), "r"(a[3]), "r"(b[0]), "r"(b[1]));
}
__device__ __forceinline__ void ldsm4(uint32_t* r, uint32_t addr) {
    asm volatile("ldmatrix.sync.aligned.m8n8.x4.shared.b16 {%0,%1,%2,%3}, [%4];"
        : "=r"(r[0]), "=r"(r[1]), "=r"(r[2]), "=r"(r[3]) : "r"(addr));
}
__device__ __forceinline__ void ldsm2(uint32_t* r, uint32_t addr) {
    asm volatile("ldmatrix.sync.aligned.m8n8.x2.shared.b16 {%0,%1}, [%2];"
        : "=r"(r[0]), "=r"(r[1]) : "r"(addr));
}

__global__ void __launch_bounds__(256) gemm1_mma_kernel(const float* __restrict__ A,
                                                        const float* __restrict__ bias,
                                                        float* __restrict__ C) {
    __shared__ __nv_bfloat16 sAhi[128 * ASTR];
    __shared__ __nv_bfloat16 sAlo[128 * ASTR];
    __shared__ __nv_bfloat16 sBhi[128 * ASTR];
    __shared__ __nv_bfloat16 sBlo[128 * ASTR];

    int tid  = threadIdx.x;
    int lane = tid & 31;
    int warp = tid >> 5;
    int wm = warp >> 1;      // 0..3
    int wn = warp & 1;       // 0..1
    int bm = blockIdx.x * 128;
    int bn = blockIdx.y * 128;

    float acc[2][8][4];
    #pragma unroll
    for (int mt = 0; mt < 2; mt++)
        #pragma unroll
        for (int nt = 0; nt < 8; nt++)
            #pragma unroll
            for (int q = 0; q < 4; q++) acc[mt][nt][q] = 0.f;

    uint32_t uAhi = smem_u32(sAhi), uAlo = smem_u32(sAlo);
    uint32_t uBhi = smem_u32(sBhi), uBlo = smem_u32(sBlo);

    // ldmatrix lane bases
    uint32_t aoff = (uint32_t)((wm * 32 + (lane & 15)) * ASTR + (lane >> 4) * 8) * 2;
    int bl = lane & 15;
    uint32_t boff = (uint32_t)((wn * 64 + (bl & 7)) * ASTR + (bl >> 3) * 8) * 2;

    for (int k0 = 0; k0 < N_FEATS; k0 += 32) {
        // ---- load A tile (fp32 -> bf16 hi/lo) : 128 rows x 32 cols ----
        #pragma unroll
        for (int it = 0; it < 4; it++) {
            int idx = tid + it * 256;        // 0..1023
            int row = idx >> 3;
            int c4  = (idx & 7) * 4;
            float4 v = make_float4(0.f, 0.f, 0.f, 0.f);
            if (bm + row < N_NODES)
                v = *(const float4*)&A[(size_t)(bm + row) * N_FEATS + k0 + c4];
            __nv_bfloat16 h0 = __float2bfloat16(v.x);
            __nv_bfloat16 h1 = __float2bfloat16(v.y);
            __nv_bfloat16 h2 = __float2bfloat16(v.z);
            __nv_bfloat16 h3 = __float2bfloat16(v.w);
            __nv_bfloat16 l0 = __float2bfloat16(v.x - __bfloat162float(h0));
            __nv_bfloat16 l1 = __float2bfloat16(v.y - __bfloat162float(h1));
            __nv_bfloat16 l2 = __float2bfloat16(v.z - __bfloat162float(h2));
            __nv_bfloat16 l3 = __float2bfloat16(v.w - __bfloat162float(h3));
            uint32_t e = row * ASTR + c4;
            uint2 hv, lv;
            hv.x = (uint32_t)__bfloat16_as_ushort(h0) | ((uint32_t)__bfloat16_as_ushort(h1) << 16);
            hv.y = (uint32_t)__bfloat16_as_ushort(h2) | ((uint32_t)__bfloat16_as_ushort(h3) << 16);
            lv.x = (uint32_t)__bfloat16_as_ushort(l0) | ((uint32_t)__bfloat16_as_ushort(l1) << 16);
            lv.y = (uint32_t)__bfloat16_as_ushort(l2) | ((uint32_t)__bfloat16_as_ushort(l3) << 16);
            *(uint2*)&sAhi[e] = hv;
            *(uint2*)&sAlo[e] = lv;
        }
        // ---- load B tiles (already bf16): 128 n-rows x 32 k ----
        #pragma unroll
        for (int it = 0; it < 2; it++) {
            int idx = tid + it * 256;        // 0..511
            int n   = idx >> 2;
            int c16 = (idx & 3) * 8;
            size_t g = (size_t)(bn + n) * N_FEATS + k0 + c16;
            uint32_t e = n * ASTR + c16;
            *(uint4*)&sBhi[e] = *(const uint4*)&g_w1t_hi[g];
            *(uint4*)&sBlo[e] = *(const uint4*)&g_w1t_lo[g];
        }
        __syncthreads();

        #pragma unroll
        for (int kc = 0; kc < 32; kc += 16) {
            uint32_t ahi[2][4], alo[2][4];
            #pragma unroll
            for (int mt = 0; mt < 2; mt++) {
                uint32_t ad = aoff + (uint32_t)(mt * 16 * ASTR + kc) * 2;
                ldsm4(ahi[mt], uAhi + ad);
                ldsm4(alo[mt], uAlo + ad);
            }
            #pragma unroll
            for (int nt = 0; nt < 8; nt++) {
                uint32_t bd = boff + (uint32_t)(nt * 8 * ASTR + kc) * 2;
                uint32_t bhi[2], blo[2];
                ldsm2(bhi, uBhi + bd);
                ldsm2(blo, uBlo + bd);
                #pragma unroll
                for (int mt = 0; mt < 2; mt++) {
                    mma16816(acc[mt][nt], ahi[mt], bhi);
                    mma16816(acc[mt][nt], ahi[mt], blo);
                    mma16816(acc[mt][nt], alo[mt], bhi);
                }
            }
        }
        __syncthreads();
    }

    // ---- epilogue: bias + relu ----
    int r  = lane >> 2;
    int c2 = (lane & 3) * 2;
    #pragma unroll
    for (int nt = 0; nt < 8; nt++) {
        int gcol = bn + wn * 64 + nt * 8 + c2;
        float bb0 = bias[gcol], bb1 = bias[gcol + 1];
        #pragma unroll
        for (int mt = 0; mt < 2; mt++) {
            int row0 = bm + wm * 32 + mt * 16 + r;
            if (row0 < N_NODES) {
                float2 o0 = make_float2(fmaxf(acc[mt][nt][0] + bb0, 0.f),
                                        fmaxf(acc[mt][nt][1] + bb1, 0.f));
                *(float2*)&C[(size_t)row0 * HIDDEN + gcol] = o0;
            }
            int row1 = row0 + 8;
            if (row1 < N_NODES) {
                float2 o1 = make_float2(fmaxf(acc[mt][nt][2] + bb0, 0.f),
                                        fmaxf(acc[mt][nt][3] + bb1, 0.f));
                *(float2*)&C[(size_t)row1 * HIDDEN + gcol] = o1;
            }
        }
    }
}

// ---------------- GEMM2 (SIMT fp32): C[M,64] = hmid @ W2 + b2 ----------------
template<int K, int N>
__global__ void gemm_kernel(const float* __restrict__ A, const float* __restrict__ B,
                            const float* __restrict__ bias, float* __restrict__ C, int M) {
    const int BM = 128, BN = 64, BK = 16;
    __shared__ float As[BK][BM];
    __shared__ float Bs[BK][BN];
    int tid = threadIdx.x;
    int bm = blockIdx.y * BM;
    int bn = blockIdx.x * BN;
    int tx = tid % 16;
    int ty = tid / 16;
    float acc[8][4];
    #pragma unroll
    for (int i = 0; i < 8; i++)
        #pragma unroll
        for (int j = 0; j < 4; j++) acc[i][j] = 0.f;
    int ar = tid >> 1, ak = (tid & 1) * 8, bk = tid >> 4, bn4 = (tid & 15) * 4;
    for (int k0 = 0; k0 < K; k0 += BK) {
        int grow = bm + ar;
        if (grow < M) {
            float4 v0 = *(const float4*)&A[(size_t)grow * K + k0 + ak];
            float4 v1 = *(const float4*)&A[(size_t)grow * K + k0 + ak + 4];
            As[ak + 0][ar] = v0.x; As[ak + 1][ar] = v0.y; As[ak + 2][ar] = v0.z; As[ak + 3][ar] = v0.w;
            As[ak + 4][ar] = v1.x; As[ak + 5][ar] = v1.y; As[ak + 6][ar] = v1.z; As[ak + 7][ar] = v1.w;
        } else {
            #pragma unroll
            for (int i = 0; i < 8; i++) As[ak + i][ar] = 0.f;
        }
        *(float4*)&Bs[bk][bn4] = *(const float4*)&B[(size_t)(k0 + bk) * N + bn + bn4];
        __syncthreads();
        #pragma unroll
        for (int kk = 0; kk < BK; kk++) {
            float4 a0 = *(float4*)&As[kk][ty * 8];
            float4 a1 = *(float4*)&As[kk][ty * 8 + 4];
            float4 bb = *(float4*)&Bs[kk][tx * 4];
            float a[8] = {a0.x, a0.y, a0.z, a0.w, a1.x, a1.y, a1.z, a1.w};
            float b[4] = {bb.x, bb.y, bb.z, bb.w};
            #pragma unroll
            for (int i = 0; i < 8; i++)
                #pragma unroll
                for (int j = 0; j < 4; j++)
                    acc[i][j] += a[i] * b[j];
        }
        __syncthreads();
    }
    float bsv[4];
    #pragma unroll
    for (int j = 0; j < 4; j++) bsv[j] = bias[bn + tx * 4 + j];
    #pragma unroll
    for (int i = 0; i < 8; i++) {
        int row = bm + ty * 8 + i;
        if (row < M) {
            float4 o = make_float4(acc[i][0] + bsv[0], acc[i][1] + bsv[1],
                                   acc[i][2] + bsv[2], acc[i][3] + bsv[3]);
            *(float4*)&C[(size_t)row * N + bn + tx * 4] = o;
        }
    }
}

// ---------------- APPNP step: half-warp per node, float4 lanes, segment masks ----------------
__device__ __forceinline__ float4 step_body16(int node, int hl, unsigned mk,
                                              const float4* __restrict__ hc4) {
    int beg = g_rowptr[node];
    int end = g_rowptr[node + 1];
    float ax = 0.f, ay = 0.f, az = 0.f, aw = 0.f;
    for (int e0 = beg; e0 < end; e0 += 16) {
        int idx = e0 + hl;
        float2 meta = (idx < end) ? g_csr[idx] : make_float2(__int_as_float(0), 0.f);
        int   srcreg = __float_as_int(meta.x);
        float wreg   = meta.y;
        #pragma unroll
        for (int j = 0; j < 16; j++) {
            int   s = __shfl_sync(mk, srcreg, j, 16);
            float w = __shfl_sync(mk, wreg,   j, 16);
            float4 hv = hc4[(size_t)s * 16 + hl];
            ax = fmaf(w, hv.x, ax);
            ay = fmaf(w, hv.y, ay);
            az = fmaf(w, hv.z, az);
            aw = fmaf(w, hv.w, aw);
        }
    }
    float dv = g_dinv[node];
    float sw = (1.0f - ALPHA) * dv * dv;
    float4 hs  = hc4[(size_t)node * 16 + hl];
    const float4* h04 = (const float4*)g_h0;
    float4 h0v = h04[(size_t)node * 16 + hl];
    float4 o;
    o.x = ax + sw * hs.x + ALPHA * h0v.x;
    o.y = ay + sw * hs.y + ALPHA * h0v.y;
    o.z = az + sw * hs.z + ALPHA * h0v.z;
    o.w = aw + sw * hs.w + ALPHA * h0v.w;
    return o;
}

__global__ void __launch_bounds__(256) step_kernel(const float4* __restrict__ hc,
                                                   float4* __restrict__ hn) {
    int gt = blockIdx.x * blockDim.x + threadIdx.x;
    int node = gt >> 4;
    int hl = threadIdx.x & 15;
    unsigned mk = 0xFFFFu << (threadIdx.x & 16);
    if (node >= N_NODES) return;
    hn[(size_t)node * 16 + hl] = step_body16(node, hl, mk, hc);
}

__global__ void __launch_bounds__(256) step_last_kernel(const float4* __restrict__ hc,
                                                        float* __restrict__ out) {
    int gt = blockIdx.x * blockDim.x + threadIdx.x;
    int node = gt >> 4;
    int hl = threadIdx.x & 15;
    unsigned mk = 0xFFFFu << (threadIdx.x & 16);
    if (node >= N_NODES) return;
    float4 v = step_body16(node, hl, mk, hc);
    float m = fmaxf(fmaxf(v.x, v.y), fmaxf(v.z, v.w));
    #pragma unroll
    for (int off = 8; off > 0; off >>= 1)
        m = fmaxf(m, __shfl_xor_sync(mk, m, off, 16));
    float s = expf(v.x - m) + expf(v.y - m) + expf(v.z - m) + expf(v.w - m);
    #pragma unroll
    for (int off = 8; off > 0; off >>= 1)
        s += __shfl_xor_sync(mk, s, off, 16);
    float ls = logf(s) + m;
    float4 o = make_float4(v.x - ls, v.y - ls, v.z - ls, v.w - ls);
    *(float4*)&out[(size_t)node * 64 + 4 * hl] = o;
}

// ---------------- launch ----------------
extern "C" void kernel_launch(void* const* d_in, const int* in_sizes, int n_in,
                              void* d_out, int out_size) {
    const float* x  = (const float*)d_in[0];
    const int*   ei = (const int*)d_in[1];
    const float* W1 = (const float*)d_in[2];
    const float* b1 = (const float*)d_in[3];
    const float* W2 = (const float*)d_in[4];
    const float* b2 = (const float*)d_in[5];
    float* out = (float*)d_out;

    void *p_hmid, *p_h0, *p_ha, *p_hb;
    cudaGetSymbolAddress(&p_hmid, g_hmid);
    cudaGetSymbolAddress(&p_h0,   g_h0);
    cudaGetSymbolAddress(&p_ha,   g_ha);
    cudaGetSymbolAddress(&p_hb,   g_hb);
    float* hmid = (float*)p_hmid;
    float* h0   = (float*)p_h0;

    splitT_w1_kernel<<<(N_FEATS * HIDDEN + 255) / 256, 256>>>(W1);     // 0
    init_deg_kernel<<<(N_NODES + 255) / 256, 256>>>();                 // 1
    count_deg_kernel<<<(N_EDGES + 255) / 256, 256>>>(ei);              // 2
    {
        dim3 grid((N_NODES + 127) / 128, HIDDEN / 128);
        gemm1_mma_kernel<<<grid, 256>>>(x, b1, hmid);                  // 3 <- profile target
    }
    dinv_kernel<<<(N_NODES + 255) / 256, 256>>>();                     // 4
    block_scan_kernel<<<SCAN_BLOCKS, 1024>>>();                        // 5
    scan_sums_kernel<<<1, 128>>>();                                    // 6
    add_off_kernel<<<(N_NODES + 255) / 256, 256>>>();                  // 7
    scatter_kernel<<<(N_EDGES + 255) / 256, 256>>>(ei);                // 8

    {
        dim3 grid2(N_CLASSES / 64, (N_NODES + 127) / 128);
        gemm_kernel<HIDDEN, N_CLASSES><<<grid2, 256>>>(hmid, W2, b2, h0, N_NODES);
    }

    int sblocks = (N_NODES * 16 + 255) / 256;
    const float4* cur = (const float4*)h0;
    float4* bufs[2] = {(float4*)p_ha, (float4*)p_hb};
    for (int t = 0; t < K_STEPS - 1; t++) {
        float4* nxt = bufs[t & 1];
        step_kernel<<<sblocks, 256>>>(cur, nxt);
        cur = nxt;
    }
    step_last_kernel<<<sblocks, 256>>>(cur, out);
}

// round 9
// speedup vs baseline: 1.6567x; 1.0810x over previous
#include <cuda_runtime.h>
#include <cuda_bf16.h>
#include <cstdint>

#define N_NODES   100000
#define N_EDGES   3200000
#define N_FEATS   512
#define HIDDEN    256
#define N_CLASSES 64
#define K_STEPS   10
#define ALPHA     0.1f

#define SCAN_BLOCKS 98   // 98*1024 >= N_NODES

// ---------------- static device scratch ----------------
__device__ float  g_hmid[(size_t)N_NODES * HIDDEN];
__device__ __align__(16) float g_h0[(size_t)N_NODES * N_CLASSES];
__device__ __align__(16) float g_ha[(size_t)N_NODES * N_CLASSES];
__device__ __align__(16) float g_hb[(size_t)N_NODES * N_CLASSES];
__device__ int    g_deg [N_NODES];
__device__ float  g_dinv[N_NODES];
__device__ int    g_rowptr[N_NODES + 1];
__device__ int    g_woff[N_NODES];
__device__ float2 g_csr[N_EDGES];   // .x=__int_as_float(src), .y=(1-alpha)*dinv*dinv
__device__ int    g_bsum[128];
__device__ int    g_boff[128];
__device__ __align__(16) __nv_bfloat16 g_xhi[(size_t)N_NODES * N_FEATS];
__device__ __align__(16) __nv_bfloat16 g_xlo[(size_t)N_NODES * N_FEATS];
__device__ __align__(16) __nv_bfloat16 g_w1t_hi[(size_t)HIDDEN * N_FEATS];  // [n][k]
__device__ __align__(16) __nv_bfloat16 g_w1t_lo[(size_t)HIDDEN * N_FEATS];

__device__ __forceinline__ uint32_t smem_u32(const void* p) {
    uint32_t a;
    asm("{ .reg .u64 t; cvta.to.shared.u64 t, %1; cvt.u32.u64 %0, t; }" : "=r"(a) : "l"(p));
    return a;
}
// SW128 swizzle on byte offsets within a 128B-row tile
__device__ __forceinline__ uint32_t sw128(uint32_t off) {
    return off ^ ((off >> 3) & 0x70);
}
__device__ __forceinline__ void cpasync16(uint32_t dst, const void* src, int srcsize) {
    asm volatile("cp.async.cg.shared.global [%0], [%1], 16, %2;"
                 :: "r"(dst), "l"(src), "r"(srcsize) : "memory");
}
#define CP_COMMIT() asm volatile("cp.async.commit_group;" ::: "memory")
#define CP_WAIT1()  asm volatile("cp.async.wait_group 1;" ::: "memory")

// ---------------- split kernels ----------------
__global__ void split_x_kernel(const float* __restrict__ x) {
    size_t n = (size_t)N_NODES * N_FEATS;
    for (size_t i = blockIdx.x * (size_t)blockDim.x + threadIdx.x; i < n;
         i += (size_t)gridDim.x * blockDim.x) {
        float v = x[i];
        __nv_bfloat16 h = __float2bfloat16(v);
        g_xhi[i] = h;
        g_xlo[i] = __float2bfloat16(v - __bfloat162float(h));
    }
}
__global__ void splitT_w1_kernel(const float* __restrict__ W1) {
    int i = blockIdx.x * blockDim.x + threadIdx.x;
    if (i >= N_FEATS * HIDDEN) return;
    int k = i / HIDDEN, n = i % HIDDEN;
    float v = W1[i];
    __nv_bfloat16 h = __float2bfloat16(v);
    g_w1t_hi[(size_t)n * N_FEATS + k] = h;
    g_w1t_lo[(size_t)n * N_FEATS + k] = __float2bfloat16(v - __bfloat162float(h));
}

// ---------------- graph preprocessing ----------------
__global__ void init_deg_kernel() {
    int i = blockIdx.x * blockDim.x + threadIdx.x;
    if (i < N_NODES) g_deg[i] = 1;
}
__global__ void count_deg_kernel(const int* __restrict__ ei) {
    int e = blockIdx.x * blockDim.x + threadIdx.x;
    if (e < N_EDGES) atomicAdd(&g_deg[ei[N_EDGES + e]], 1);
}
__global__ void dinv_kernel() {
    int i = blockIdx.x * blockDim.x + threadIdx.x;
    if (i < N_NODES) g_dinv[i] = rsqrtf((float)g_deg[i]);
}
__global__ void block_scan_kernel() {
    __shared__ int s[1024];
    int t = threadIdx.x;
    int i = blockIdx.x * 1024 + t;
    int v = (i < N_NODES) ? (g_deg[i] - 1) : 0;
    s[t] = v;
    __syncthreads();
    #pragma unroll
    for (int off = 1; off < 1024; off <<= 1) {
        int add = (t >= off) ? s[t - off] : 0;
        __syncthreads();
        s[t] += add;
        __syncthreads();
    }
    if (i < N_NODES) g_rowptr[i] = s[t] - v;
    if (t == 1023) g_bsum[blockIdx.x] = s[t];
}
__global__ void scan_sums_kernel() {
    __shared__ int s[128];
    int t = threadIdx.x;
    int v = (t < SCAN_BLOCKS) ? g_bsum[t] : 0;
    s[t] = v;
    __syncthreads();
    #pragma unroll
    for (int off = 1; off < 128; off <<= 1) {
        int add = (t >= off) ? s[t - off] : 0;
        __syncthreads();
        s[t] += add;
        __syncthreads();
    }
    g_boff[t] = s[t] - v;
}
__global__ void add_off_kernel() {
    int i = blockIdx.x * blockDim.x + threadIdx.x;
    if (i < N_NODES) {
        int r = g_rowptr[i] + g_boff[i >> 10];
        g_rowptr[i] = r;
        g_woff[i]   = r;
    }
    if (i == 0) g_rowptr[N_NODES] = N_EDGES;
}
__global__ void scatter_kernel(const int* __restrict__ ei) {
    int e = blockIdx.x * blockDim.x + threadIdx.x;
    if (e >= N_EDGES) return;
    int s = ei[e];
    int d = ei[N_EDGES + e];
    float w = (1.0f - ALPHA) * g_dinv[s] * g_dinv[d];
    int pos = atomicAdd(&g_woff[d], 1);
    g_csr[pos] = make_float2(__int_as_float(s), w);
}

// ---------------- GEMM1: mma.sync bf16 3-split, cp.async 2-stage pipeline ----------------
// BM=128 BN=128 BK=64, SW128 smem (128B rows), 8 warps 4Mx2N.
#define G1_NCHUNK (N_FEATS / 64)        // 8
#define TILE16K   16384                 // 128 rows * 128 B
#define STAGE_B   (4 * TILE16K)         // Ahi, Alo, Bhi, Blo
#define G1_SMEM   (2 * STAGE_B)         // 131072

__device__ __forceinline__ void mma16816(float* c, const uint32_t* a, const uint32_t* b) {
    asm volatile("mma.sync.aligned.m16n8k16.row.col.f32.bf16.bf16.f32 "
        "{%0,%1,%2,%3},{%4,%5,%6,%7},{%8,%9},{%0,%1,%2,%3};"
        : "+f"(c[0]), "+f"(c[1]), "+f"(c[2]), "+f"(c[3])
        : "r"(a[0]), "r"(a[1]), "r"(a[2]), "r"(a[3]), "r"(b[0]), "r"(b[1]));
}
__device__ __forceinline__ void ldsm4(uint32_t* r, uint32_t addr) {
    asm volatile("ldmatrix.sync.aligned.m8n8.x4.shared.b16 {%0,%1,%2,%3}, [%4];"
        : "=r"(r[0]), "=r"(r[1]), "=r"(r[2]), "=r"(r[3]) : "r"(addr));
}

__global__ void __launch_bounds__(256, 1) gemm1_mma_kernel(const float* __restrict__ bias,
                                                           float* __restrict__ C) {
    extern __shared__ char smem[];
    uint32_t sb = smem_u32(smem);
    int tid  = threadIdx.x;
    int lane = tid & 31;
    int warp = tid >> 5;
    int wm = warp >> 1;      // 0..3 (M)
    int wn = warp & 1;       // 0..1 (N)
    int bm = blockIdx.x * 128;
    int bn = blockIdx.y * 128;

    float acc[2][8][4];
    #pragma unroll
    for (int mt = 0; mt < 2; mt++)
        #pragma unroll
        for (int nt = 0; nt < 8; nt++)
            #pragma unroll
            for (int q = 0; q < 4; q++) acc[mt][nt][q] = 0.f;

    // per-thread load coords: 4 chunks of 16B per tile per stage
    int lrow = tid >> 3;         // 0..31 base row (x4 iters of +32)
    int lch  = tid & 7;          // 16B chunk in row

    // issue loads for chunk c into stage s
    auto load_stage = [&](int c, int s) {
        uint32_t base = sb + s * STAGE_B;
        int k8 = c * 64 + lch * 8;   // element offset in k
        #pragma unroll
        for (int j = 0; j < 4; j++) {
            int row = lrow + j * 32;
            uint32_t soff = sw128((uint32_t)(row * 128 + lch * 16));
            int grow = bm + row;
            int valid = grow < N_NODES;
            int gr = valid ? grow : 0;
            int vs = valid ? 16 : 0;
            cpasync16(base + soff,               &g_xhi[(size_t)gr * N_FEATS + k8], vs);
            cpasync16(base + TILE16K + soff,     &g_xlo[(size_t)gr * N_FEATS + k8], vs);
            cpasync16(base + 2 * TILE16K + soff, &g_w1t_hi[(size_t)(bn + row) * N_FEATS + k8], 16);
            cpasync16(base + 3 * TILE16K + soff, &g_w1t_lo[(size_t)(bn + row) * N_FEATS + k8], 16);
        }
    };

    load_stage(0, 0);
    CP_COMMIT();

    // ldmatrix lane bases
    int arow = wm * 32 + (lane & 15);
    int akb  = (lane >> 4) * 16;          // 0 or 16 bytes (k half)
    int bg   = lane >> 3;                  // 0..3
    int brow = wn * 64 + (bg & 1) * 8 + (lane & 7);
    int bkb  = (bg >> 1) * 16;

    for (int c = 0; c < G1_NCHUNK; c++) {
        int s = c & 1;
        if (c + 1 < G1_NCHUNK) load_stage(c + 1, (c + 1) & 1);
        CP_COMMIT();
        CP_WAIT1();
        __syncthreads();

        uint32_t uAhi = sb + s * STAGE_B;
        uint32_t uAlo = uAhi + TILE16K;
        uint32_t uBhi = uAhi + 2 * TILE16K;
        uint32_t uBlo = uAhi + 3 * TILE16K;

        #pragma unroll
        for (int kc = 0; kc < 64; kc += 16) {
            uint32_t ahi[2][4], alo[2][4];
            #pragma unroll
            for (int mt = 0; mt < 2; mt++) {
                uint32_t ao = sw128((uint32_t)((arow + mt * 16) * 128 + kc * 2 + akb));
                ldsm4(ahi[mt], uAhi + ao);
                ldsm4(alo[mt], uAlo + ao);
            }
            #pragma unroll
            for (int ntp = 0; ntp < 4; ntp++) {
                uint32_t bo = sw128((uint32_t)((brow + ntp * 16) * 128 + kc * 2 + bkb));
                uint32_t bh[4], bl[4];
                ldsm4(bh, uBhi + bo);
                ldsm4(bl, uBlo + bo);
                // bh = {b0(nt0), b0(nt1), b1(nt0), b1(nt1)}
                uint32_t b0h[2] = {bh[0], bh[2]}, b1h[2] = {bh[1], bh[3]};
                uint32_t b0l[2] = {bl[0], bl[2]}, b1l[2] = {bl[1], bl[3]};
                #pragma unroll
                for (int mt = 0; mt < 2; mt++) {
                    mma16816(acc[mt][2 * ntp],     ahi[mt], b0h);
                    mma16816(acc[mt][2 * ntp],     ahi[mt], b0l);
                    mma16816(acc[mt][2 * ntp],     alo[mt], b0h);
                    mma16816(acc[mt][2 * ntp + 1], ahi[mt], b1h);
                    mma16816(acc[mt][2 * ntp + 1], ahi[mt], b1l);
                    mma16816(acc[mt][2 * ntp + 1], alo[mt], b1h);
                }
            }
        }
        __syncthreads();
    }

    // ---- epilogue: bias + relu ----
    int r  = lane >> 2;
    int c2 = (lane & 3) * 2;
    #pragma unroll
    for (int nt = 0; nt < 8; nt++) {
        int gcol = bn + wn * 64 + nt * 8 + c2;
        float bb0 = bias[gcol], bb1 = bias[gcol + 1];
        #pragma unroll
        for (int mt = 0; mt < 2; mt++) {
            int row0 = bm + wm * 32 + mt * 16 + r;
            if (row0 < N_NODES) {
                float2 o0 = make_float2(fmaxf(acc[mt][nt][0] + bb0, 0.f),
                                        fmaxf(acc[mt][nt][1] + bb1, 0.f));
                *(float2*)&C[(size_t)row0 * HIDDEN + gcol] = o0;
            }
            int row1 = row0 + 8;
            if (row1 < N_NODES) {
                float2 o1 = make_float2(fmaxf(acc[mt][nt][2] + bb0, 0.f),
                                        fmaxf(acc[mt][nt][3] + bb1, 0.f));
                *(float2*)&C[(size_t)row1 * HIDDEN + gcol] = o1;
            }
        }
    }
}

// ---------------- GEMM2 (SIMT fp32): C[M,64] = hmid @ W2 + b2 ----------------
template<int K, int N>
__global__ void gemm_kernel(const float* __restrict__ A, const float* __restrict__ B,
                            const float* __restrict__ bias, float* __restrict__ C, int M) {
    const int BM = 128, BN = 64, BK = 16;
    __shared__ float As[BK][BM];
    __shared__ float Bs[BK][BN];
    int tid = threadIdx.x;
    int bm = blockIdx.y * BM;
    int bn = blockIdx.x * BN;
    int tx = tid % 16;
    int ty = tid / 16;
    float acc[8][4];
    #pragma unroll
    for (int i = 0; i < 8; i++)
        #pragma unroll
        for (int j = 0; j < 4; j++) acc[i][j] = 0.f;
    int ar = tid >> 1, ak = (tid & 1) * 8, bk = tid >> 4, bn4 = (tid & 15) * 4;
    for (int k0 = 0; k0 < K; k0 += BK) {
        int grow = bm + ar;
        if (grow < M) {
            float4 v0 = *(const float4*)&A[(size_t)grow * K + k0 + ak];
            float4 v1 = *(const float4*)&A[(size_t)grow * K + k0 + ak + 4];
            As[ak + 0][ar] = v0.x; As[ak + 1][ar] = v0.y; As[ak + 2][ar] = v0.z; As[ak + 3][ar] = v0.w;
            As[ak + 4][ar] = v1.x; As[ak + 5][ar] = v1.y; As[ak + 6][ar] = v1.z; As[ak + 7][ar] = v1.w;
        } else {
            #pragma unroll
            for (int i = 0; i < 8; i++) As[ak + i][ar] = 0.f;
        }
        *(float4*)&Bs[bk][bn4] = *(const float4*)&B[(size_t)(k0 + bk) * N + bn + bn4];
        __syncthreads();
        #pragma unroll
        for (int kk = 0; kk < BK; kk++) {
            float4 a0 = *(float4*)&As[kk][ty * 8];
            float4 a1 = *(float4*)&As[kk][ty * 8 + 4];
            float4 bb = *(float4*)&Bs[kk][tx * 4];
            float a[8] = {a0.x, a0.y, a0.z, a0.w, a1.x, a1.y, a1.z, a1.w};
            float b[4] = {bb.x, bb.y, bb.z, bb.w};
            #pragma unroll
            for (int i = 0; i < 8; i++)
                #pragma unroll
                for (int j = 0; j < 4; j++)
                    acc[i][j] += a[i] * b[j];
        }
        __syncthreads();
    }
    float bsv[4];
    #pragma unroll
    for (int j = 0; j < 4; j++) bsv[j] = bias[bn + tx * 4 + j];
    #pragma unroll
    for (int i = 0; i < 8; i++) {
        int row = bm + ty * 8 + i;
        if (row < M) {
            float4 o = make_float4(acc[i][0] + bsv[0], acc[i][1] + bsv[1],
                                   acc[i][2] + bsv[2], acc[i][3] + bsv[3]);
            *(float4*)&C[(size_t)row * N + bn + tx * 4] = o;
        }
    }
}

// ---------------- APPNP step: half-warp per node, float4 lanes, segment masks ----------------
__device__ __forceinline__ float4 step_body16(int node, int hl, unsigned mk,
                                              const float4* __restrict__ hc4) {
    int beg = g_rowptr[node];
    int end = g_rowptr[node + 1];
    float ax = 0.f, ay = 0.f, az = 0.f, aw = 0.f;
    for (int e0 = beg; e0 < end; e0 += 16) {
        int idx = e0 + hl;
        float2 meta = (idx < end) ? g_csr[idx] : make_float2(__int_as_float(0), 0.f);
        int   srcreg = __float_as_int(meta.x);
        float wreg   = meta.y;
        #pragma unroll
        for (int j = 0; j < 16; j++) {
            int   s = __shfl_sync(mk, srcreg, j, 16);
            float w = __shfl_sync(mk, wreg,   j, 16);
            float4 hv = hc4[(size_t)s * 16 + hl];
            ax = fmaf(w, hv.x, ax);
            ay = fmaf(w, hv.y, ay);
            az = fmaf(w, hv.z, az);
            aw = fmaf(w, hv.w, aw);
        }
    }
    float dv = g_dinv[node];
    float sw = (1.0f - ALPHA) * dv * dv;
    float4 hs  = hc4[(size_t)node * 16 + hl];
    const float4* h04 = (const float4*)g_h0;
    float4 h0v = h04[(size_t)node * 16 + hl];
    float4 o;
    o.x = ax + sw * hs.x + ALPHA * h0v.x;
    o.y = ay + sw * hs.y + ALPHA * h0v.y;
    o.z = az + sw * hs.z + ALPHA * h0v.z;
    o.w = aw + sw * hs.w + ALPHA * h0v.w;
    return o;
}

__global__ void __launch_bounds__(256) step_kernel(const float4* __restrict__ hc,
                                                   float4* __restrict__ hn) {
    int gt = blockIdx.x * blockDim.x + threadIdx.x;
    int node = gt >> 4;
    int hl = threadIdx.x & 15;
    unsigned mk = 0xFFFFu << (threadIdx.x & 16);
    if (node >= N_NODES) return;
    hn[(size_t)node * 16 + hl] = step_body16(node, hl, mk, hc);
}

__global__ void __launch_bounds__(256) step_last_kernel(const float4* __restrict__ hc,
                                                        float* __restrict__ out) {
    int gt = blockIdx.x * blockDim.x + threadIdx.x;
    int node = gt >> 4;
    int hl = threadIdx.x & 15;
    unsigned mk = 0xFFFFu << (threadIdx.x & 16);
    if (node >= N_NODES) return;
    float4 v = step_body16(node, hl, mk, hc);
    float m = fmaxf(fmaxf(v.x, v.y), fmaxf(v.z, v.w));
    #pragma unroll
    for (int off = 8; off > 0; off >>= 1)
        m = fmaxf(m, __shfl_xor_sync(mk, m, off, 16));
    float s = expf(v.x - m) + expf(v.y - m) + expf(v.z - m) + expf(v.w - m);
    #pragma unroll
    for (int off = 8; off > 0; off >>= 1)
        s += __shfl_xor_sync(mk, s, off, 16);
    float ls = logf(s) + m;
    float4 o = make_float4(v.x - ls, v.y - ls, v.z - ls, v.w - ls);
    *(float4*)&out[(size_t)node * 64 + 4 * hl] = o;
}

// ---------------- launch ----------------
extern "C" void kernel_launch(void* const* d_in, const int* in_sizes, int n_in,
                              void* d_out, int out_size) {
    const float* x  = (const float*)d_in[0];
    const int*   ei = (const int*)d_in[1];
    const float* W1 = (const float*)d_in[2];
    const float* b1 = (const float*)d_in[3];
    const float* W2 = (const float*)d_in[4];
    const float* b2 = (const float*)d_in[5];
    float* out = (float*)d_out;

    void *p_hmid, *p_h0, *p_ha, *p_hb;
    cudaGetSymbolAddress(&p_hmid, g_hmid);
    cudaGetSymbolAddress(&p_h0,   g_h0);
    cudaGetSymbolAddress(&p_ha,   g_ha);
    cudaGetSymbolAddress(&p_hb,   g_hb);
    float* hmid = (float*)p_hmid;
    float* h0   = (float*)p_h0;

    static bool attr_done = false;
    if (!attr_done) {
        cudaFuncSetAttribute(gemm1_mma_kernel,
                             cudaFuncAttributeMaxDynamicSharedMemorySize, G1_SMEM);
        attr_done = true;
    }

    split_x_kernel<<<512, 256>>>(x);                                   // 0
    splitT_w1_kernel<<<(N_FEATS * HIDDEN + 255) / 256, 256>>>(W1);     // 1
    init_deg_kernel<<<(N_NODES + 255) / 256, 256>>>();                 // 2
    {
        dim3 grid((N_NODES + 127) / 128, HIDDEN / 128);
        gemm1_mma_kernel<<<grid, 256, G1_SMEM>>>(b1, hmid);            // 3 <- profile target
    }
    count_deg_kernel<<<(N_EDGES + 255) / 256, 256>>>(ei);              // 4
    dinv_kernel<<<(N_NODES + 255) / 256, 256>>>();                     // 5
    block_scan_kernel<<<SCAN_BLOCKS, 1024>>>();                        // 6
    scan_sums_kernel<<<1, 128>>>();                                    // 7
    add_off_kernel<<<(N_NODES + 255) / 256, 256>>>();                  // 8
    scatter_kernel<<<(N_EDGES + 255) / 256, 256>>>(ei);                // 9

    {
        dim3 grid2(N_CLASSES / 64, (N_NODES + 127) / 128);
        gemm_kernel<HIDDEN, N_CLASSES><<<grid2, 256>>>(hmid, W2, b2, h0, N_NODES);
    }

    int sblocks = (N_NODES * 16 + 255) / 256;
    const float4* cur = (const float4*)h0;
    float4* bufs[2] = {(float4*)p_ha, (float4*)p_hb};
    for (int t = 0; t < K_STEPS - 1; t++) {
        float4* nxt = bufs[t & 1];
        step_kernel<<<sblocks, 256>>>(cur, nxt);
        cur = nxt;
    }
    step_last_kernel<<<sblocks, 256>>>(cur, out);
}

// round 12
// speedup vs baseline: 1.7862x; 1.0781x over previous
#include <cuda_runtime.h>
#include <cuda_bf16.h>
#include <cstdint>

#define N_NODES   100000
#define N_EDGES   3200000
#define N_FEATS   512
#define HIDDEN    256
#define N_CLASSES 64
#define K_STEPS   10
#define ALPHA     0.1f

#define SCAN_BLOCKS 98   // 98*1024 >= N_NODES

// ---------------- static device scratch ----------------
// hs buffers have ONE EXTRA ROW (index N_NODES) kept at zero: dummy gather target.
__device__ __align__(16) float g_h0[(size_t)N_NODES * N_CLASSES];              // alpha*h0
__device__ __align__(16) float g_ha[((size_t)N_NODES + 1) * N_CLASSES];        // hs buffers
__device__ __align__(16) float g_hb[((size_t)N_NODES + 1) * N_CLASSES];
__device__ int    g_deg [N_NODES];
__device__ float  g_dinv[N_NODES];
__device__ int    g_rowptr[N_NODES + 1];
__device__ int    g_woff[N_NODES];
__device__ int    g_csr_src[N_EDGES];
__device__ int    g_bsum[128];
__device__ int    g_boff[128];
__device__ __align__(16) __nv_bfloat16 g_xhi[(size_t)N_NODES * N_FEATS];
__device__ __align__(16) __nv_bfloat16 g_xlo[(size_t)N_NODES * N_FEATS];
__device__ __align__(16) __nv_bfloat16 g_w1t_hi[(size_t)HIDDEN * N_FEATS];     // [n][k]
__device__ __align__(16) __nv_bfloat16 g_w1t_lo[(size_t)HIDDEN * N_FEATS];
__device__ __align__(16) __nv_bfloat16 g_hmid_hi[(size_t)N_NODES * HIDDEN];    // gemm1 out (split)
__device__ __align__(16) __nv_bfloat16 g_hmid_lo[(size_t)N_NODES * HIDDEN];
__device__ __align__(16) __nv_bfloat16 g_w2t_hi[(size_t)N_CLASSES * HIDDEN];   // [n][k]
__device__ __align__(16) __nv_bfloat16 g_w2t_lo[(size_t)N_CLASSES * HIDDEN];

__device__ __forceinline__ uint32_t smem_u32(const void* p) {
    uint32_t a;
    asm("{ .reg .u64 t; cvta.to.shared.u64 t, %1; cvt.u32.u64 %0, t; }" : "=r"(a) : "l"(p));
    return a;
}
__device__ __forceinline__ uint32_t sw128(uint32_t off) {
    return off ^ ((off >> 3) & 0x70);
}
__device__ __forceinline__ void cpasync16(uint32_t dst, const void* src, int srcsize) {
    asm volatile("cp.async.cg.shared.global [%0], [%1], 16, %2;"
                 :: "r"(dst), "l"(src), "r"(srcsize) : "memory");
}
#define CP_COMMIT() asm volatile("cp.async.commit_group;" ::: "memory")
#define CP_WAIT1()  asm volatile("cp.async.wait_group 1;" ::: "memory")
#define CP_WAIT0()  asm volatile("cp.async.wait_group 0;" ::: "memory")

__device__ __forceinline__ void mma16816(float* c, const uint32_t* a, const uint32_t* b) {
    asm volatile("mma.sync.aligned.m16n8k16.row.col.f32.bf16.bf16.f32 "
        "{%0,%1,%2,%3},{%4,%5,%6,%7},{%8,%9},{%0,%1,%2,%3};"
        : "+f"(c[0]), "+f"(c[1]), "+f"(c[2]), "+f"(c[3])
        : "r"(a[0]), "r"(a[1]), "r"(a[2]), "r"(a[3]), "r"(b[0]), "r"(b[1]));
}
__device__ __forceinline__ void ldsm4(uint32_t* r, uint32_t addr) {
    asm volatile("ldmatrix.sync.aligned.m8n8.x4.shared.b16 {%0,%1,%2,%3}, [%4];"
        : "=r"(r[0]), "=r"(r[1]), "=r"(r[2]), "=r"(r[3]) : "r"(addr));
}

// ---------------- split kernels ----------------
__global__ void split_x_kernel(const float* __restrict__ x) {
    size_t n = (size_t)N_NODES * N_FEATS;
    for (size_t i = blockIdx.x * (size_t)blockDim.x + threadIdx.x; i < n;
         i += (size_t)gridDim.x * blockDim.x) {
        float v = x[i];
        __nv_bfloat16 h = __float2bfloat16(v);
        g_xhi[i] = h;
        g_xlo[i] = __float2bfloat16(v - __bfloat162float(h));
    }
}
__global__ void splitT_w1_kernel(const float* __restrict__ W1) {
    int i = blockIdx.x * blockDim.x + threadIdx.x;
    if (i >= N_FEATS * HIDDEN) return;
    int k = i / HIDDEN, n = i % HIDDEN;
    float v = W1[i];
    __nv_bfloat16 h = __float2bfloat16(v);
    g_w1t_hi[(size_t)n * N_FEATS + k] = h;
    g_w1t_lo[(size_t)n * N_FEATS + k] = __float2bfloat16(v - __bfloat162float(h));
}
__global__ void splitT_w2_kernel(const float* __restrict__ W2) {
    int i = blockIdx.x * blockDim.x + threadIdx.x;
    if (i >= HIDDEN * N_CLASSES) return;
    int k = i / N_CLASSES, n = i % N_CLASSES;
    float v = W2[i];
    __nv_bfloat16 h = __float2bfloat16(v);
    g_w2t_hi[(size_t)n * HIDDEN + k] = h;
    g_w2t_lo[(size_t)n * HIDDEN + k] = __float2bfloat16(v - __bfloat162float(h));
}
__global__ void zero_pad_kernel() {
    int i = threadIdx.x;
    if (i < N_CLASSES) {
        g_ha[(size_t)N_NODES * N_CLASSES + i] = 0.f;
        g_hb[(size_t)N_NODES * N_CLASSES + i] = 0.f;
    }
}

// ---------------- graph preprocessing ----------------
__global__ void init_deg_kernel() {
    int i = blockIdx.x * blockDim.x + threadIdx.x;
    if (i < N_NODES) g_deg[i] = 1;
}
__global__ void count_deg_kernel(const int* __restrict__ ei) {
    int e = blockIdx.x * blockDim.x + threadIdx.x;
    if (e < N_EDGES) atomicAdd(&g_deg[ei[N_EDGES + e]], 1);
}
__global__ void dinv_kernel() {
    int i = blockIdx.x * blockDim.x + threadIdx.x;
    if (i < N_NODES) g_dinv[i] = rsqrtf((float)g_deg[i]);
}
__global__ void block_scan_kernel() {
    __shared__ int s[1024];
    int t = threadIdx.x;
    int i = blockIdx.x * 1024 + t;
    int v = (i < N_NODES) ? (g_deg[i] - 1) : 0;
    s[t] = v;
    __syncthreads();
    #pragma unroll
    for (int off = 1; off < 1024; off <<= 1) {
        int add = (t >= off) ? s[t - off] : 0;
        __syncthreads();
        s[t] += add;
        __syncthreads();
    }
    if (i < N_NODES) g_rowptr[i] = s[t] - v;
    if (t == 1023) g_bsum[blockIdx.x] = s[t];
}
__global__ void scan_sums_kernel() {
    __shared__ int s[128];
    int t = threadIdx.x;
    int v = (t < SCAN_BLOCKS) ? g_bsum[t] : 0;
    s[t] = v;
    __syncthreads();
    #pragma unroll
    for (int off = 1; off < 128; off <<= 1) {
        int add = (t >= off) ? s[t - off] : 0;
        __syncthreads();
        s[t] += add;
        __syncthreads();
    }
    g_boff[t] = s[t] - v;
}
__global__ void add_off_kernel() {
    int i = blockIdx.x * blockDim.x + threadIdx.x;
    if (i < N_NODES) {
        int r = g_rowptr[i] + g_boff[i >> 10];
        g_rowptr[i] = r;
        g_woff[i]   = r;
    }
    if (i == 0) g_rowptr[N_NODES] = N_EDGES;
}
__global__ void scatter_kernel(const int* __restrict__ ei) {
    int e = blockIdx.x * blockDim.x + threadIdx.x;
    if (e >= N_EDGES) return;
    int s = ei[e];
    int d = ei[N_EDGES + e];
    int pos = atomicAdd(&g_woff[d], 1);
    g_csr_src[pos] = s;
}

// ---------------- GEMM1: bf16 3-split mma, 3-stage cp.async, 1 sync/chunk ----------------
// BM=128 BN=128 BK=64, SW128 smem, 8 warps 4Mx2N. Writes hmid as bf16 hi/lo split.
#define G1_NCHUNK (N_FEATS / 64)        // 8
#define TILE16K   16384                 // 128 rows * 128 B
#define STAGE_B   (4 * TILE16K)         // Ahi, Alo, Bhi, Blo
#define G1_SMEM   (3 * STAGE_B)         // 196608

__global__ void __launch_bounds__(256, 1) gemm1_mma_kernel(const float* __restrict__ bias) {
    extern __shared__ char smem[];
    uint32_t sb = smem_u32(smem);
    int tid  = threadIdx.x;
    int lane = tid & 31;
    int warp = tid >> 5;
    int wm = warp >> 1;
    int wn = warp & 1;
    int bm = blockIdx.x * 128;
    int bn = blockIdx.y * 128;

    float acc[2][8][4];
    #pragma unroll
    for (int mt = 0; mt < 2; mt++)
        #pragma unroll
        for (int nt = 0; nt < 8; nt++)
            #pragma unroll
            for (int q = 0; q < 4; q++) acc[mt][nt][q] = 0.f;

    int lrow = tid >> 3;
    int lch  = tid & 7;

    auto load_stage = [&](int c, int s) {
        uint32_t base = sb + s * STAGE_B;
        int k8 = c * 64 + lch * 8;
        #pragma unroll
        for (int j = 0; j < 4; j++) {
            int row = lrow + j * 32;
            uint32_t soff = sw128((uint32_t)(row * 128 + lch * 16));
            int grow = bm + row;
            int valid = grow < N_NODES;
            int gr = valid ? grow : 0;
            int vs = valid ? 16 : 0;
            cpasync16(base + soff,               &g_xhi[(size_t)gr * N_FEATS + k8], vs);
            cpasync16(base + TILE16K + soff,     &g_xlo[(size_t)gr * N_FEATS + k8], vs);
            cpasync16(base + 2 * TILE16K + soff, &g_w1t_hi[(size_t)(bn + row) * N_FEATS + k8], 16);
            cpasync16(base + 3 * TILE16K + soff, &g_w1t_lo[(size_t)(bn + row) * N_FEATS + k8], 16);
        }
    };

    load_stage(0, 0); CP_COMMIT();
    load_stage(1, 1); CP_COMMIT();

    int arow = wm * 32 + (lane & 15);
    int akb  = (lane >> 4) * 16;
    int bg   = lane >> 3;
    int brow = wn * 64 + (bg & 1) * 8 + (lane & 7);
    int bkb  = (bg >> 1) * 16;

    for (int c = 0; c < G1_NCHUNK; c++) {
        CP_WAIT1();
        __syncthreads();
        if (c + 2 < G1_NCHUNK) load_stage(c + 2, (c + 2) % 3);
        CP_COMMIT();

        int s = c % 3;
        uint32_t uAhi = sb + s * STAGE_B;
        uint32_t uAlo = uAhi + TILE16K;
        uint32_t uBhi = uAhi + 2 * TILE16K;
        uint32_t uBlo = uAhi + 3 * TILE16K;

        #pragma unroll
        for (int kc = 0; kc < 64; kc += 16) {
            uint32_t ahi[2][4], alo[2][4];
            #pragma unroll
            for (int mt = 0; mt < 2; mt++) {
                uint32_t ao = sw128((uint32_t)((arow + mt * 16) * 128 + kc * 2 + akb));
                ldsm4(ahi[mt], uAhi + ao);
                ldsm4(alo[mt], uAlo + ao);
            }
            #pragma unroll
            for (int ntp = 0; ntp < 4; ntp++) {
                uint32_t bo = sw128((uint32_t)((brow + ntp * 16) * 128 + kc * 2 + bkb));
                uint32_t bh[4], bl[4];
                ldsm4(bh, uBhi + bo);
                ldsm4(bl, uBlo + bo);
                uint32_t b0h[2] = {bh[0], bh[2]}, b1h[2] = {bh[1], bh[3]};
                uint32_t b0l[2] = {bl[0], bl[2]}, b1l[2] = {bl[1], bl[3]};
                #pragma unroll
                for (int mt = 0; mt < 2; mt++) {
                    mma16816(acc[mt][2 * ntp],     ahi[mt], b0h);
                    mma16816(acc[mt][2 * ntp],     ahi[mt], b0l);
                    mma16816(acc[mt][2 * ntp],     alo[mt], b0h);
                    mma16816(acc[mt][2 * ntp + 1], ahi[mt], b1h);
                    mma16816(acc[mt][2 * ntp + 1], ahi[mt], b1l);
                    mma16816(acc[mt][2 * ntp + 1], alo[mt], b1h);
                }
            }
        }
    }

    // ---- epilogue: bias + relu, write bf16 hi/lo split ----
    int r  = lane >> 2;
    int c2 = (lane & 3) * 2;
    #pragma unroll
    for (int nt = 0; nt < 8; nt++) {
        int gcol = bn + wn * 64 + nt * 8 + c2;
        float bb0 = bias[gcol], bb1 = bias[gcol + 1];
        #pragma unroll
        for (int mt = 0; mt < 2; mt++) {
            #pragma unroll
            for (int half = 0; half < 2; half++) {
                int row = bm + wm * 32 + mt * 16 + r + half * 8;
                if (row < N_NODES) {
                    float v0 = fmaxf(acc[mt][nt][2 * half]     + bb0, 0.f);
                    float v1 = fmaxf(acc[mt][nt][2 * half + 1] + bb1, 0.f);
                    __nv_bfloat16 h0 = __float2bfloat16(v0);
                    __nv_bfloat16 h1 = __float2bfloat16(v1);
                    __nv_bfloat16 l0 = __float2bfloat16(v0 - __bfloat162float(h0));
                    __nv_bfloat16 l1 = __float2bfloat16(v1 - __bfloat162float(h1));
                    uint32_t hv = (uint32_t)__bfloat16_as_ushort(h0) |
                                  ((uint32_t)__bfloat16_as_ushort(h1) << 16);
                    uint32_t lv = (uint32_t)__bfloat16_as_ushort(l0) |
                                  ((uint32_t)__bfloat16_as_ushort(l1) << 16);
                    *(uint32_t*)&g_hmid_hi[(size_t)row * HIDDEN + gcol] = hv;
                    *(uint32_t*)&g_hmid_lo[(size_t)row * HIDDEN + gcol] = lv;
                }
            }
        }
    }
}

// ---------------- GEMM2: bf16 3-split mma, single-shot smem (K=256, N=64) ----------------
// Writes: g_h0 = alpha*(hmid@W2+b2),  g_ha = dinv*(hmid@W2+b2)  (= hs0)
#define G2_A_HI 0
#define G2_A_LO 65536
#define G2_B_HI 131072
#define G2_B_LO 163840
#define G2_SMEM 196608

__global__ void __launch_bounds__(256, 1) gemm2_mma_kernel(const float* __restrict__ bias) {
    extern __shared__ char smem[];
    uint32_t sb = smem_u32(smem);
    int tid  = threadIdx.x;
    int lane = tid & 31;
    int warp = tid >> 5;
    int wm = warp >> 1;     // 0..3 (M)
    int wn = warp & 1;      // 0..1 (N)
    int bm = blockIdx.x * 128;

    // load A (hmid hi/lo): 128 rows x 256 k.  Row = 512B = 32 chunks of 16B;
    // each SW128 k-block row is 128B = 8 chunks -> kblk = c16>>3, sub = c16&7.
    #pragma unroll
    for (int it = 0; it < 16; it++) {
        int idx = tid + it * 256;
        int row = idx >> 5;
        int c16 = idx & 31;
        int kblk = c16 >> 3, sub = c16 & 7;
        uint32_t soff = sw128((uint32_t)((kblk * 128 + row) * 128 + sub * 16));
        int grow = bm + row;
        int valid = grow < N_NODES;
        int gr = valid ? grow : 0;
        int vs = valid ? 16 : 0;
        cpasync16(sb + G2_A_HI + soff, &g_hmid_hi[(size_t)gr * HIDDEN + kblk * 64 + sub * 8], vs);
        cpasync16(sb + G2_A_LO + soff, &g_hmid_lo[(size_t)gr * HIDDEN + kblk * 64 + sub * 8], vs);
    }
    // load B (w2t hi/lo): 64 rows x 256 k (same row decomposition)
    #pragma unroll
    for (int it = 0; it < 8; it++) {
        int idx = tid + it * 256;
        int row = idx >> 5;
        int c16 = idx & 31;
        int kblk = c16 >> 3, sub = c16 & 7;
        uint32_t soff = sw128((uint32_t)((kblk * 64 + row) * 128 + sub * 16));
        cpasync16(sb + G2_B_HI + soff, &g_w2t_hi[(size_t)row * HIDDEN + kblk * 64 + sub * 8], 16);
        cpasync16(sb + G2_B_LO + soff, &g_w2t_lo[(size_t)row * HIDDEN + kblk * 64 + sub * 8], 16);
    }
    CP_COMMIT();
    CP_WAIT0();
    __syncthreads();

    float acc[2][4][4];
    #pragma unroll
    for (int mt = 0; mt < 2; mt++)
        #pragma unroll
        for (int nt = 0; nt < 4; nt++)
            #pragma unroll
            for (int q = 0; q < 4; q++) acc[mt][nt][q] = 0.f;

    int arow = wm * 32 + (lane & 15);
    int akb  = (lane >> 4) * 16;
    int bg   = lane >> 3;
    int brow = wn * 32 + (bg & 1) * 8 + (lane & 7);
    int bkb  = (bg >> 1) * 16;

    #pragma unroll
    for (int kc = 0; kc < HIDDEN; kc += 16) {
        int kblk = kc >> 6, kin = kc & 63;
        uint32_t ahi[2][4], alo[2][4];
        #pragma unroll
        for (int mt = 0; mt < 2; mt++) {
            uint32_t ao = sw128((uint32_t)((kblk * 128 + arow + mt * 16) * 128 + kin * 2 + akb));
            ldsm4(ahi[mt], sb + G2_A_HI + ao);
            ldsm4(alo[mt], sb + G2_A_LO + ao);
        }
        #pragma unroll
        for (int ntp = 0; ntp < 2; ntp++) {
            uint32_t bo = sw128((uint32_t)((kblk * 64 + brow + ntp * 16) * 128 + kin * 2 + bkb));
            uint32_t bh[4], bl[4];
            ldsm4(bh, sb + G2_B_HI + bo);
            ldsm4(bl, sb + G2_B_LO + bo);
            uint32_t b0h[2] = {bh[0], bh[2]}, b1h[2] = {bh[1], bh[3]};
            uint32_t b0l[2] = {bl[0], bl[2]}, b1l[2] = {bl[1], bl[3]};
            #pragma unroll
            for (int mt = 0; mt < 2; mt++) {
                mma16816(acc[mt][2 * ntp],     ahi[mt], b0h);
                mma16816(acc[mt][2 * ntp],     ahi[mt], b0l);
                mma16816(acc[mt][2 * ntp],     alo[mt], b0h);
                mma16816(acc[mt][2 * ntp + 1], ahi[mt], b1h);
                mma16816(acc[mt][2 * ntp + 1], ahi[mt], b1l);
                mma16816(acc[mt][2 * ntp + 1], alo[mt], b1h);
            }
        }
    }

    // epilogue: val = acc + bias; write alpha*val and dinv*val
    int r  = lane >> 2;
    int c2 = (lane & 3) * 2;
    #pragma unroll
    for (int nt = 0; nt < 4; nt++) {
        int gcol = wn * 32 + nt * 8 + c2;
        float bb0 = bias[gcol], bb1 = bias[gcol + 1];
        #pragma unroll
        for (int mt = 0; mt < 2; mt++) {
            #pragma unroll
            for (int half = 0; half < 2; half++) {
                int row = bm + wm * 32 + mt * 16 + r + half * 8;
                if (row < N_NODES) {
                    float v0 = acc[mt][nt][2 * half]     + bb0;
                    float v1 = acc[mt][nt][2 * half + 1] + bb1;
                    float d  = g_dinv[row];
                    *(float2*)&g_h0[(size_t)row * N_CLASSES + gcol] =
                        make_float2(ALPHA * v0, ALPHA * v1);
                    *(float2*)&g_ha[(size_t)row * N_CLASSES + gcol] =
                        make_float2(d * v0, d * v1);
                }
            }
        }
    }
}

// ---------------- APPNP step: half-warp per node, src-only CSR, dummy zero row ----------------
// buffers hold hs = dinv*h.  val = 0.9*dinv*(sum + hs_self) + alpha*h0;  next hs = dinv*val
__device__ __forceinline__ void step_core(int node, int hl, unsigned mk,
                                          const float4* __restrict__ hc4,
                                          float4& val, float& dv) {
    int beg = g_rowptr[node];
    int end = g_rowptr[node + 1];
    float ax = 0.f, ay = 0.f, az = 0.f, aw = 0.f;
    for (int e0 = beg; e0 < end; e0 += 16) {
        int idx = e0 + hl;
        int src = (idx < end) ? g_csr_src[idx] : N_NODES;   // dummy zero row
        #pragma unroll
        for (int j = 0; j < 16; j++) {
            int s = __shfl_sync(mk, src, j, 16);
            float4 hv = hc4[(size_t)s * 16 + hl];
            ax += hv.x; ay += hv.y; az += hv.z; aw += hv.w;
        }
    }
    dv = g_dinv[node];
    float4 hs = hc4[(size_t)node * 16 + hl];
    const float4* ah4 = (const float4*)g_h0;
    float4 ah = ah4[(size_t)node * 16 + hl];
    float coef = (1.0f - ALPHA) * dv;
    val.x = fmaf(coef, ax + hs.x, ah.x);
    val.y = fmaf(coef, ay + hs.y, ah.y);
    val.z = fmaf(coef, az + hs.z, ah.z);
    val.w = fmaf(coef, aw + hs.w, ah.w);
}

__global__ void __launch_bounds__(256) step_kernel(const float4* __restrict__ hc,
                                                   float4* __restrict__ hn) {
    int gt = blockIdx.x * blockDim.x + threadIdx.x;
    int node = gt >> 4;
    int hl = threadIdx.x & 15;
    unsigned mk = 0xFFFFu << (threadIdx.x & 16);
    if (node >= N_NODES) return;
    float4 val; float dv;
    step_core(node, hl, mk, hc, val, dv);
    hn[(size_t)node * 16 + hl] = make_float4(dv * val.x, dv * val.y, dv * val.z, dv * val.w);
}

__global__ void __launch_bounds__(256) step_last_kernel(const float4* __restrict__ hc,
                                                        float* __restrict__ out) {
    int gt = blockIdx.x * blockDim.x + threadIdx.x;
    int node = gt >> 4;
    int hl = threadIdx.x & 15;
    unsigned mk = 0xFFFFu << (threadIdx.x & 16);
    if (node >= N_NODES) return;
    float4 v; float dv;
    step_core(node, hl, mk, hc, v, dv);
    float m = fmaxf(fmaxf(v.x, v.y), fmaxf(v.z, v.w));
    #pragma unroll
    for (int off = 8; off > 0; off >>= 1)
        m = fmaxf(m, __shfl_xor_sync(mk, m, off, 16));
    float s = expf(v.x - m) + expf(v.y - m) + expf(v.z - m) + expf(v.w - m);
    #pragma unroll
    for (int off = 8; off > 0; off >>= 1)
        s += __shfl_xor_sync(mk, s, off, 16);
    float ls = logf(s) + m;
    float4 o = make_float4(v.x - ls, v.y - ls, v.z - ls, v.w - ls);
    *(float4*)&out[(size_t)node * 64 + 4 * hl] = o;
}

// ---------------- launch ----------------
extern "C" void kernel_launch(void* const* d_in, const int* in_sizes, int n_in,
                              void* d_out, int out_size) {
    const float* x  = (const float*)d_in[0];
    const int*   ei = (const int*)d_in[1];
    const float* W1 = (const float*)d_in[2];
    const float* b1 = (const float*)d_in[3];
    const float* W2 = (const float*)d_in[4];
    const float* b2 = (const float*)d_in[5];
    float* out = (float*)d_out;

    void *p_ha, *p_hb;
    cudaGetSymbolAddress(&p_ha, g_ha);
    cudaGetSymbolAddress(&p_hb, g_hb);

    static bool attr_done = false;
    if (!attr_done) {
        cudaFuncSetAttribute(gemm1_mma_kernel,
                             cudaFuncAttributeMaxDynamicSharedMemorySize, G1_SMEM);
        cudaFuncSetAttribute(gemm2_mma_kernel,
                             cudaFuncAttributeMaxDynamicSharedMemorySize, G2_SMEM);
        attr_done = true;
    }

    split_x_kernel<<<512, 256>>>(x);                                   // 0
    splitT_w1_kernel<<<(N_FEATS * HIDDEN + 255) / 256, 256>>>(W1);     // 1
    init_deg_kernel<<<(N_NODES + 255) / 256, 256>>>();                 // 2
    {
        dim3 grid((N_NODES + 127) / 128, HIDDEN / 128);
        gemm1_mma_kernel<<<grid, 256, G1_SMEM>>>(b1);                  // 3 <- profile target
    }
    splitT_w2_kernel<<<(HIDDEN * N_CLASSES + 255) / 256, 256>>>(W2);   // 4
    count_deg_kernel<<<(N_EDGES + 255) / 256, 256>>>(ei);              // 5
    dinv_kernel<<<(N_NODES + 255) / 256, 256>>>();                     // 6
    block_scan_kernel<<<SCAN_BLOCKS, 1024>>>();                        // 7
    scan_sums_kernel<<<1, 128>>>();                                    // 8
    add_off_kernel<<<(N_NODES + 255) / 256, 256>>>();                  // 9
    scatter_kernel<<<(N_EDGES + 255) / 256, 256>>>(ei);                // 10
    zero_pad_kernel<<<1, 128>>>();                                     // 11
    gemm2_mma_kernel<<<(N_NODES + 127) / 128, 256, G2_SMEM>>>(b2);     // 12 -> writes h0(alpha) + hs0 into g_ha

    int sblocks = (N_NODES * 16 + 255) / 256;
    const float4* cur = (const float4*)p_ha;
    float4* bufs[2] = {(float4*)p_hb, (float4*)p_ha};   // t even -> hb, t odd -> ha
    for (int t = 0; t < K_STEPS - 1; t++) {
        float4* nxt = bufs[t & 1];
        step_kernel<<<sblocks, 256>>>(cur, nxt);
        cur = nxt;
    }
    step_last_kernel<<<sblocks, 256>>>(cur, out);
}

// round 17
// speedup vs baseline: 1.8137x; 1.0154x over previous
#include <cuda_runtime.h>
#include <cuda_bf16.h>
#include <cstdint>

#define N_NODES   100000
#define N_EDGES   3200000
#define N_FEATS   512
#define HIDDEN    256
#define N_CLASSES 64
#define K_STEPS   10
#define ALPHA     0.1f

#define SCAN_BLOCKS 98   // 98*1024 >= N_NODES

// ---------------- static device scratch ----------------
// hs buffers have ONE EXTRA ROW (index N_NODES) kept at zero: dummy gather target.
__device__ __align__(16) float g_h0[(size_t)N_NODES * N_CLASSES];              // alpha*h0
__device__ __align__(16) float g_ha[((size_t)N_NODES + 1) * N_CLASSES];        // hs buffers
__device__ __align__(16) float g_hb[((size_t)N_NODES + 1) * N_CLASSES];
__device__ int    g_deg [N_NODES];
__device__ float  g_dinv[N_NODES];
__device__ int    g_rowptr[N_NODES + 1];
__device__ int    g_woff[N_NODES];
__device__ int    g_csr_src[N_EDGES];
__device__ int    g_bsum[128];
__device__ int    g_boff[128];
__device__ __align__(16) __nv_bfloat16 g_xhi[(size_t)N_NODES * N_FEATS];
__device__ __align__(16) __nv_bfloat16 g_xlo[(size_t)N_NODES * N_FEATS];
__device__ __align__(16) __nv_bfloat16 g_w1t_hi[(size_t)HIDDEN * N_FEATS];     // [n][k]
__device__ __align__(16) __nv_bfloat16 g_w1t_lo[(size_t)HIDDEN * N_FEATS];
__device__ __align__(16) __nv_bfloat16 g_hmid_hi[(size_t)N_NODES * HIDDEN];    // gemm1 out (split)
__device__ __align__(16) __nv_bfloat16 g_hmid_lo[(size_t)N_NODES * HIDDEN];
__device__ __align__(16) __nv_bfloat16 g_w2t_hi[(size_t)N_CLASSES * HIDDEN];   // [n][k]
__device__ __align__(16) __nv_bfloat16 g_w2t_lo[(size_t)N_CLASSES * HIDDEN];

__device__ __forceinline__ uint32_t smem_u32(const void* p) {
    uint32_t a;
    asm("{ .reg .u64 t; cvta.to.shared.u64 t, %1; cvt.u32.u64 %0, t; }" : "=r"(a) : "l"(p));
    return a;
}
__device__ __forceinline__ uint32_t sw128(uint32_t off) {
    return off ^ ((off >> 3) & 0x70);
}
__device__ __forceinline__ void cpasync16(uint32_t dst, const void* src, int srcsize) {
    asm volatile("cp.async.cg.shared.global [%0], [%1], 16, %2;"
                 :: "r"(dst), "l"(src), "r"(srcsize) : "memory");
}
#define CP_COMMIT() asm volatile("cp.async.commit_group;" ::: "memory")
#define CP_WAIT1()  asm volatile("cp.async.wait_group 1;" ::: "memory")
#define CP_WAIT0()  asm volatile("cp.async.wait_group 0;" ::: "memory")

__device__ __forceinline__ void mma16816(float* c, const uint32_t* a, const uint32_t* b) {
    asm volatile("mma.sync.aligned.m16n8k16.row.col.f32.bf16.bf16.f32 "
        "{%0,%1,%2,%3},{%4,%5,%6,%7},{%8,%9},{%0,%1,%2,%3};"
        : "+f"(c[0]), "+f"(c[1]), "+f"(c[2]), "+f"(c[3])
        : "r"(a[0]), "r"(a[1]), "r"(a[2]), "r"(a[3]), "r"(b[0]), "r"(b[1]));
}
__device__ __forceinline__ void ldsm4(uint32_t* r, uint32_t addr) {
    asm volatile("ldmatrix.sync.aligned.m8n8.x4.shared.b16 {%0,%1,%2,%3}, [%4];"
        : "=r"(r[0]), "=r"(r[1]), "=r"(r[2]), "=r"(r[3]) : "r"(addr));
}

// ---------------- split kernels ----------------
__global__ void split_x_kernel(const float* __restrict__ x) {
    size_t n = (size_t)N_NODES * N_FEATS;
    for (size_t i = blockIdx.x * (size_t)blockDim.x + threadIdx.x; i < n;
         i += (size_t)gridDim.x * blockDim.x) {
        float v = x[i];
        __nv_bfloat16 h = __float2bfloat16(v);
        g_xhi[i] = h;
        g_xlo[i] = __float2bfloat16(v - __bfloat162float(h));
    }
}
__global__ void splitT_w1_kernel(const float* __restrict__ W1) {
    int i = blockIdx.x * blockDim.x + threadIdx.x;
    if (i >= N_FEATS * HIDDEN) return;
    int k = i / HIDDEN, n = i % HIDDEN;
    float v = W1[i];
    __nv_bfloat16 h = __float2bfloat16(v);
    g_w1t_hi[(size_t)n * N_FEATS + k] = h;
    g_w1t_lo[(size_t)n * N_FEATS + k] = __float2bfloat16(v - __bfloat162float(h));
}
__global__ void splitT_w2_kernel(const float* __restrict__ W2) {
    int i = blockIdx.x * blockDim.x + threadIdx.x;
    if (i >= HIDDEN * N_CLASSES) return;
    int k = i / N_CLASSES, n = i % N_CLASSES;
    float v = W2[i];
    __nv_bfloat16 h = __float2bfloat16(v);
    g_w2t_hi[(size_t)n * HIDDEN + k] = h;
    g_w2t_lo[(size_t)n * HIDDEN + k] = __float2bfloat16(v - __bfloat162float(h));
}
__global__ void zero_pad_kernel() {
    int i = threadIdx.x;
    if (i < N_CLASSES) {
        g_ha[(size_t)N_NODES * N_CLASSES + i] = 0.f;
        g_hb[(size_t)N_NODES * N_CLASSES + i] = 0.f;
    }
}

// ---------------- graph preprocessing ----------------
__global__ void init_deg_kernel() {
    int i = blockIdx.x * blockDim.x + threadIdx.x;
    if (i < N_NODES) g_deg[i] = 1;
}
__global__ void count_deg_kernel(const int* __restrict__ ei) {
    int e = blockIdx.x * blockDim.x + threadIdx.x;
    if (e < N_EDGES) atomicAdd(&g_deg[ei[N_EDGES + e]], 1);
}
__global__ void dinv_kernel() {
    int i = blockIdx.x * blockDim.x + threadIdx.x;
    if (i < N_NODES) g_dinv[i] = rsqrtf((float)g_deg[i]);
}
__global__ void block_scan_kernel() {
    __shared__ int s[1024];
    int t = threadIdx.x;
    int i = blockIdx.x * 1024 + t;
    int v = (i < N_NODES) ? (g_deg[i] - 1) : 0;
    s[t] = v;
    __syncthreads();
    #pragma unroll
    for (int off = 1; off < 1024; off <<= 1) {
        int add = (t >= off) ? s[t - off] : 0;
        __syncthreads();
        s[t] += add;
        __syncthreads();
    }
    if (i < N_NODES) g_rowptr[i] = s[t] - v;
    if (t == 1023) g_bsum[blockIdx.x] = s[t];
}
__global__ void scan_sums_kernel() {
    __shared__ int s[128];
    int t = threadIdx.x;
    int v = (t < SCAN_BLOCKS) ? g_bsum[t] : 0;
    s[t] = v;
    __syncthreads();
    #pragma unroll
    for (int off = 1; off < 128; off <<= 1) {
        int add = (t >= off) ? s[t - off] : 0;
        __syncthreads();
        s[t] += add;
        __syncthreads();
    }
    g_boff[t] = s[t] - v;
}
__global__ void add_off_kernel() {
    int i = blockIdx.x * blockDim.x + threadIdx.x;
    if (i < N_NODES) {
        int r = g_rowptr[i] + g_boff[i >> 10];
        g_rowptr[i] = r;
        g_woff[i]   = r;
    }
    if (i == 0) g_rowptr[N_NODES] = N_EDGES;
}
__global__ void scatter_kernel(const int* __restrict__ ei) {
    int e = blockIdx.x * blockDim.x + threadIdx.x;
    if (e >= N_EDGES) return;
    int s = ei[e];
    int d = ei[N_EDGES + e];
    int pos = atomicAdd(&g_woff[d], 1);
    g_csr_src[pos] = s;
}

// ---------------- GEMM1: bf16 3-split mma, 512 threads, 2-stage cp.async ----------------
// BM=128 BN=128 BK=64, SW128 smem. 16 warps as 4(M)x4(N); warp tile 32x32.
#define G1_NCHUNK (N_FEATS / 64)        // 8
#define TILE16K   16384                 // 128 rows * 128 B
#define STAGE_B   (4 * TILE16K)         // Ahi, Alo, Bhi, Blo
#define G1_SMEM   (2 * STAGE_B)         // 131072

__global__ void __launch_bounds__(512, 1) gemm1_mma_kernel(const float* __restrict__ bias) {
    extern __shared__ char smem[];
    uint32_t sb = smem_u32(smem);
    int tid  = threadIdx.x;
    int lane = tid & 31;
    int warp = tid >> 5;
    int wm = warp >> 2;      // 0..3 (M band of 32 rows)
    int wn = warp & 3;       // 0..3 (N band of 32 cols)
    int bm = blockIdx.x * 128;
    int bn = blockIdx.y * 128;

    float acc[2][4][4];
    #pragma unroll
    for (int mt = 0; mt < 2; mt++)
        #pragma unroll
        for (int nt = 0; nt < 4; nt++)
            #pragma unroll
            for (int q = 0; q < 4; q++) acc[mt][nt][q] = 0.f;

    int lrow = tid >> 3;     // 0..63 base row (+64 second iter)
    int lch  = tid & 7;

    auto load_stage = [&](int c, int s) {
        uint32_t base = sb + s * STAGE_B;
        int k8 = c * 64 + lch * 8;
        #pragma unroll
        for (int j = 0; j < 2; j++) {
            int row = lrow + j * 64;
            uint32_t soff = sw128((uint32_t)(row * 128 + lch * 16));
            int grow = bm + row;
            int valid = grow < N_NODES;
            int gr = valid ? grow : 0;
            int vs = valid ? 16 : 0;
            cpasync16(base + soff,               &g_xhi[(size_t)gr * N_FEATS + k8], vs);
            cpasync16(base + TILE16K + soff,     &g_xlo[(size_t)gr * N_FEATS + k8], vs);
            cpasync16(base + 2 * TILE16K + soff, &g_w1t_hi[(size_t)(bn + row) * N_FEATS + k8], 16);
            cpasync16(base + 3 * TILE16K + soff, &g_w1t_lo[(size_t)(bn + row) * N_FEATS + k8], 16);
        }
    };

    load_stage(0, 0);
    CP_COMMIT();

    int arow = wm * 32 + (lane & 15);
    int akb  = (lane >> 4) * 16;
    int bg   = lane >> 3;
    int brow = wn * 32 + (bg & 1) * 8 + (lane & 7);
    int bkb  = (bg >> 1) * 16;

    for (int c = 0; c < G1_NCHUNK; c++) {
        int s = c & 1;
        if (c + 1 < G1_NCHUNK) load_stage(c + 1, (c + 1) & 1);
        CP_COMMIT();
        CP_WAIT1();
        __syncthreads();

        uint32_t uAhi = sb + s * STAGE_B;
        uint32_t uAlo = uAhi + TILE16K;
        uint32_t uBhi = uAhi + 2 * TILE16K;
        uint32_t uBlo = uAhi + 3 * TILE16K;

        #pragma unroll
        for (int kc = 0; kc < 64; kc += 16) {
            uint32_t ahi[2][4], alo[2][4];
            #pragma unroll
            for (int mt = 0; mt < 2; mt++) {
                uint32_t ao = sw128((uint32_t)((arow + mt * 16) * 128 + kc * 2 + akb));
                ldsm4(ahi[mt], uAhi + ao);
                ldsm4(alo[mt], uAlo + ao);
            }
            #pragma unroll
            for (int ntp = 0; ntp < 2; ntp++) {
                uint32_t bo = sw128((uint32_t)((brow + ntp * 16) * 128 + kc * 2 + bkb));
                uint32_t bh[4], bl[4];
                ldsm4(bh, uBhi + bo);
                ldsm4(bl, uBlo + bo);
                uint32_t b0h[2] = {bh[0], bh[2]}, b1h[2] = {bh[1], bh[3]};
                uint32_t b0l[2] = {bl[0], bl[2]}, b1l[2] = {bl[1], bl[3]};
                #pragma unroll
                for (int mt = 0; mt < 2; mt++) {
                    mma16816(acc[mt][2 * ntp],     ahi[mt], b0h);
                    mma16816(acc[mt][2 * ntp],     ahi[mt], b0l);
                    mma16816(acc[mt][2 * ntp],     alo[mt], b0h);
                    mma16816(acc[mt][2 * ntp + 1], ahi[mt], b1h);
                    mma16816(acc[mt][2 * ntp + 1], ahi[mt], b1l);
                    mma16816(acc[mt][2 * ntp + 1], alo[mt], b1h);
                }
            }
        }
        __syncthreads();
    }

    // ---- epilogue: bias + relu, write bf16 hi/lo split ----
    int r  = lane >> 2;
    int c2 = (lane & 3) * 2;
    #pragma unroll
    for (int nt = 0; nt < 4; nt++) {
        int gcol = bn + wn * 32 + nt * 8 + c2;
        float bb0 = bias[gcol], bb1 = bias[gcol + 1];
        #pragma unroll
        for (int mt = 0; mt < 2; mt++) {
            #pragma unroll
            for (int half = 0; half < 2; half++) {
                int row = bm + wm * 32 + mt * 16 + r + half * 8;
                if (row < N_NODES) {
                    float v0 = fmaxf(acc[mt][nt][2 * half]     + bb0, 0.f);
                    float v1 = fmaxf(acc[mt][nt][2 * half + 1] + bb1, 0.f);
                    __nv_bfloat16 h0 = __float2bfloat16(v0);
                    __nv_bfloat16 h1 = __float2bfloat16(v1);
                    __nv_bfloat16 l0 = __float2bfloat16(v0 - __bfloat162float(h0));
                    __nv_bfloat16 l1 = __float2bfloat16(v1 - __bfloat162float(h1));
                    uint32_t hv = (uint32_t)__bfloat16_as_ushort(h0) |
                                  ((uint32_t)__bfloat16_as_ushort(h1) << 16);
                    uint32_t lv = (uint32_t)__bfloat16_as_ushort(l0) |
                                  ((uint32_t)__bfloat16_as_ushort(l1) << 16);
                    *(uint32_t*)&g_hmid_hi[(size_t)row * HIDDEN + gcol] = hv;
                    *(uint32_t*)&g_hmid_lo[(size_t)row * HIDDEN + gcol] = lv;
                }
            }
        }
    }
}

// ---------------- GEMM2: bf16 3-split mma, single-shot smem (K=256, N=64) ----------------
// Writes: g_h0 = alpha*(hmid@W2+b2),  g_ha = dinv*(hmid@W2+b2)  (= hs0)
#define G2_A_HI 0
#define G2_A_LO 65536
#define G2_B_HI 131072
#define G2_B_LO 163840
#define G2_SMEM 196608

__global__ void __launch_bounds__(256, 1) gemm2_mma_kernel(const float* __restrict__ bias) {
    extern __shared__ char smem[];
    uint32_t sb = smem_u32(smem);
    int tid  = threadIdx.x;
    int lane = tid & 31;
    int warp = tid >> 5;
    int wm = warp >> 1;     // 0..3 (M)
    int wn = warp & 1;      // 0..1 (N)
    int bm = blockIdx.x * 128;

    // load A (hmid hi/lo): row = 512B = 32 chunks of 16B; kblk = c16>>3, sub = c16&7
    #pragma unroll
    for (int it = 0; it < 16; it++) {
        int idx = tid + it * 256;
        int row = idx >> 5;
        int c16 = idx & 31;
        int kblk = c16 >> 3, sub = c16 & 7;
        uint32_t soff = sw128((uint32_t)((kblk * 128 + row) * 128 + sub * 16));
        int grow = bm + row;
        int valid = grow < N_NODES;
        int gr = valid ? grow : 0;
        int vs = valid ? 16 : 0;
        cpasync16(sb + G2_A_HI + soff, &g_hmid_hi[(size_t)gr * HIDDEN + kblk * 64 + sub * 8], vs);
        cpasync16(sb + G2_A_LO + soff, &g_hmid_lo[(size_t)gr * HIDDEN + kblk * 64 + sub * 8], vs);
    }
    // load B (w2t hi/lo): 64 rows x 256 k
    #pragma unroll
    for (int it = 0; it < 8; it++) {
        int idx = tid + it * 256;
        int row = idx >> 5;
        int c16 = idx & 31;
        int kblk = c16 >> 3, sub = c16 & 7;
        uint32_t soff = sw128((uint32_t)((kblk * 64 + row) * 128 + sub * 16));
        cpasync16(sb + G2_B_HI + soff, &g_w2t_hi[(size_t)row * HIDDEN + kblk * 64 + sub * 8], 16);
        cpasync16(sb + G2_B_LO + soff, &g_w2t_lo[(size_t)row * HIDDEN + kblk * 64 + sub * 8], 16);
    }
    CP_COMMIT();
    CP_WAIT0();
    __syncthreads();

    float acc[2][4][4];
    #pragma unroll
    for (int mt = 0; mt < 2; mt++)
        #pragma unroll
        for (int nt = 0; nt < 4; nt++)
            #pragma unroll
            for (int q = 0; q < 4; q++) acc[mt][nt][q] = 0.f;

    int arow = wm * 32 + (lane & 15);
    int akb  = (lane >> 4) * 16;
    int bg   = lane >> 3;
    int brow = wn * 32 + (bg & 1) * 8 + (lane & 7);
    int bkb  = (bg >> 1) * 16;

    #pragma unroll
    for (int kc = 0; kc < HIDDEN; kc += 16) {
        int kblk = kc >> 6, kin = kc & 63;
        uint32_t ahi[2][4], alo[2][4];
        #pragma unroll
        for (int mt = 0; mt < 2; mt++) {
            uint32_t ao = sw128((uint32_t)((kblk * 128 + arow + mt * 16) * 128 + kin * 2 + akb));
            ldsm4(ahi[mt], sb + G2_A_HI + ao);
            ldsm4(alo[mt], sb + G2_A_LO + ao);
        }
        #pragma unroll
        for (int ntp = 0; ntp < 2; ntp++) {
            uint32_t bo = sw128((uint32_t)((kblk * 64 + brow + ntp * 16) * 128 + kin * 2 + bkb));
            uint32_t bh[4], bl[4];
            ldsm4(bh, sb + G2_B_HI + bo);
            ldsm4(bl, sb + G2_B_LO + bo);
            uint32_t b0h[2] = {bh[0], bh[2]}, b1h[2] = {bh[1], bh[3]};
            uint32_t b0l[2] = {bl[0], bl[2]}, b1l[2] = {bl[1], bl[3]};
            #pragma unroll
            for (int mt = 0; mt < 2; mt++) {
                mma16816(acc[mt][2 * ntp],     ahi[mt], b0h);
                mma16816(acc[mt][2 * ntp],     ahi[mt], b0l);
                mma16816(acc[mt][2 * ntp],     alo[mt], b0h);
                mma16816(acc[mt][2 * ntp + 1], ahi[mt], b1h);
                mma16816(acc[mt][2 * ntp + 1], ahi[mt], b1l);
                mma16816(acc[mt][2 * ntp + 1], alo[mt], b1h);
            }
        }
    }

    // epilogue: val = acc + bias; write alpha*val and dinv*val
    int r  = lane >> 2;
    int c2 = (lane & 3) * 2;
    #pragma unroll
    for (int nt = 0; nt < 4; nt++) {
        int gcol = wn * 32 + nt * 8 + c2;
        float bb0 = bias[gcol], bb1 = bias[gcol + 1];
        #pragma unroll
        for (int mt = 0; mt < 2; mt++) {
            #pragma unroll
            for (int half = 0; half < 2; half++) {
                int row = bm + wm * 32 + mt * 16 + r + half * 8;
                if (row < N_NODES) {
                    float v0 = acc[mt][nt][2 * half]     + bb0;
                    float v1 = acc[mt][nt][2 * half + 1] + bb1;
                    float d  = g_dinv[row];
                    *(float2*)&g_h0[(size_t)row * N_CLASSES + gcol] =
                        make_float2(ALPHA * v0, ALPHA * v1);
                    *(float2*)&g_ha[(size_t)row * N_CLASSES + gcol] =
                        make_float2(d * v0, d * v1);
                }
            }
        }
    }
}

// ---------------- APPNP step: half-warp per node, src-only CSR, dummy zero row ----------------
// buffers hold hs = dinv*h.  val = 0.9*dinv*(sum + hs_self) + alpha*h0;  next hs = dinv*val
__device__ __forceinline__ void step_core(int node, int hl, unsigned mk,
                                          const float4* __restrict__ hc4,
                                          float4& val, float& dv) {
    int beg = g_rowptr[node];
    int end = g_rowptr[node + 1];
    float ax = 0.f, ay = 0.f, az = 0.f, aw = 0.f;
    for (int e0 = beg; e0 < end; e0 += 16) {
        int idx = e0 + hl;
        int src = (idx < end) ? g_csr_src[idx] : N_NODES;   // dummy zero row
        #pragma unroll
        for (int j = 0; j < 16; j++) {
            int s = __shfl_sync(mk, src, j, 16);
            float4 hv = hc4[(size_t)s * 16 + hl];
            ax += hv.x; ay += hv.y; az += hv.z; aw += hv.w;
        }
    }
    dv = g_dinv[node];
    float4 hs = hc4[(size_t)node * 16 + hl];
    const float4* ah4 = (const float4*)g_h0;
    float4 ah = ah4[(size_t)node * 16 + hl];
    float coef = (1.0f - ALPHA) * dv;
    val.x = fmaf(coef, ax + hs.x, ah.x);
    val.y = fmaf(coef, ay + hs.y, ah.y);
    val.z = fmaf(coef, az + hs.z, ah.z);
    val.w = fmaf(coef, aw + hs.w, ah.w);
}

__global__ void __launch_bounds__(256) step_kernel(const float4* __restrict__ hc,
                                                   float4* __restrict__ hn) {
    int gt = blockIdx.x * blockDim.x + threadIdx.x;
    int node = gt >> 4;
    int hl = threadIdx.x & 15;
    unsigned mk = 0xFFFFu << (threadIdx.x & 16);
    if (node >= N_NODES) return;
    float4 val; float dv;
    step_core(node, hl, mk, hc, val, dv);
    hn[(size_t)node * 16 + hl] = make_float4(dv * val.x, dv * val.y, dv * val.z, dv * val.w);
}

__global__ void __launch_bounds__(256) step_last_kernel(const float4* __restrict__ hc,
                                                        float* __restrict__ out) {
    int gt = blockIdx.x * blockDim.x + threadIdx.x;
    int node = gt >> 4;
    int hl = threadIdx.x & 15;
    unsigned mk = 0xFFFFu << (threadIdx.x & 16);
    if (node >= N_NODES) return;
    float4 v; float dv;
    step_core(node, hl, mk, hc, v, dv);
    float m = fmaxf(fmaxf(v.x, v.y), fmaxf(v.z, v.w));
    #pragma unroll
    for (int off = 8; off > 0; off >>= 1)
        m = fmaxf(m, __shfl_xor_sync(mk, m, off, 16));
    float s = expf(v.x - m) + expf(v.y - m) + expf(v.z - m) + expf(v.w - m);
    #pragma unroll
    for (int off = 8; off > 0; off >>= 1)
        s += __shfl_xor_sync(mk, s, off, 16);
    float ls = logf(s) + m;
    float4 o = make_float4(v.x - ls, v.y - ls, v.z - ls, v.w - ls);
    *(float4*)&out[(size_t)node * 64 + 4 * hl] = o;
}

// ---------------- launch ----------------
extern "C" void kernel_launch(void* const* d_in, const int* in_sizes, int n_in,
                              void* d_out, int out_size) {
    const float* x  = (const float*)d_in[0];
    const int*   ei = (const int*)d_in[1];
    const float* W1 = (const float*)d_in[2];
    const float* b1 = (const float*)d_in[3];
    const float* W2 = (const float*)d_in[4];
    const float* b2 = (const float*)d_in[5];
    float* out = (float*)d_out;

    void *p_ha, *p_hb;
    cudaGetSymbolAddress(&p_ha, g_ha);
    cudaGetSymbolAddress(&p_hb, g_hb);

    static bool attr_done = false;
    if (!attr_done) {
        cudaFuncSetAttribute(gemm1_mma_kernel,
                             cudaFuncAttributeMaxDynamicSharedMemorySize, G1_SMEM);
        cudaFuncSetAttribute(gemm2_mma_kernel,
                             cudaFuncAttributeMaxDynamicSharedMemorySize, G2_SMEM);
        attr_done = true;
    }

    split_x_kernel<<<512, 256>>>(x);                                   // 0
    splitT_w1_kernel<<<(N_FEATS * HIDDEN + 255) / 256, 256>>>(W1);     // 1
    init_deg_kernel<<<(N_NODES + 255) / 256, 256>>>();                 // 2
    {
        dim3 grid((N_NODES + 127) / 128, HIDDEN / 128);
        gemm1_mma_kernel<<<grid, 512, G1_SMEM>>>(b1);                  // 3 <- profile target
    }
    splitT_w2_kernel<<<(HIDDEN * N_CLASSES + 255) / 256, 256>>>(W2);   // 4
    count_deg_kernel<<<(N_EDGES + 255) / 256, 256>>>(ei);              // 5
    dinv_kernel<<<(N_NODES + 255) / 256, 256>>>();                     // 6
    block_scan_kernel<<<SCAN_BLOCKS, 1024>>>();                        // 7
    scan_sums_kernel<<<1, 128>>>();                                    // 8
    add_off_kernel<<<(N_NODES + 255) / 256, 256>>>();                  // 9
    scatter_kernel<<<(N_EDGES + 255) / 256, 256>>>(ei);                // 10
    zero_pad_kernel<<<1, 128>>>();                                     // 11
    gemm2_mma_kernel<<<(N_NODES + 127) / 128, 256, G2_SMEM>>>(b2);     // 12

    int sblocks = (N_NODES * 16 + 255) / 256;
    const float4* cur = (const float4*)p_ha;
    float4* bufs[2] = {(float4*)p_hb, (float4*)p_ha};   // t even -> hb, t odd -> ha
    for (int t = 0; t < K_STEPS - 1; t++) {
        float4* nxt = bufs[t & 1];
        step_kernel<<<sblocks, 256>>>(cur, nxt);
        cur = nxt;
    }
    step_last_kernel<<<sblocks, 256>>>(cur, out);
}